// round 1
// baseline (speedup 1.0000x reference)
#include <cuda_runtime.h>
#include <math.h>

// ---------------- problem constants ----------------
static constexpr int BB   = 4;
static constexpr int KK   = 256;
static constexpr int NS   = 1024;      // seeds
static constexpr int CF   = 256;       // seed feature channels
static constexpr int GPP  = 64;        // grid points per proposal
static constexpr int QQ   = KK * GPP;  // 16384 queries per batch
static constexpr int M1   = BB * QQ;   // 65536 rows for conv layers
static constexpr int CIN0 = CF + 3;    // 259
static constexpr int LDA0 = 272;       // padded leading dim for X0
static constexpr int HH   = 128;
static constexpr int MFC  = BB * KK;   // 1024 rows for FC layers
static constexpr int IOUS = 18;
static constexpr int OUTC = 77;

// ---------------- scratch (static device memory; no allocations) ----------------
__device__ float g_X0[(long long)M1 * LDA0];   // [M1, 259(+pad)] channel-last input
__device__ float g_wq[M1 * 3];                 // query points
__device__ float g_featT[BB * NS * CF];        // transposed seed features [b][n][c]
__device__ int   g_idx3[M1 * 3];
__device__ float g_w3[M1 * 3];
__device__ float g_Y1[(long long)M1 * HH];
__device__ float g_Y2[(long long)M1 * HH];
__device__ float g_Y3[(long long)M1 * HH];
__device__ float g_F [MFC * HH];
__device__ float g_N1[MFC * HH];
__device__ float g_N2[MFC * HH];
__device__ float g_part[128 * 256];            // per-block partial BN stats
__device__ float g_scale[5 * 128];             // folded BN scale per layer
__device__ float g_shift[5 * 128];             // folded BN shift per layer

// ---------------- kernels ----------------

// seed_features [b][c][n] -> g_featT [b][n][c]
__global__ void k_transpose(const float* __restrict__ feat) {
    __shared__ float tile[32][33];
    int b  = blockIdx.z;
    int n0 = blockIdx.x * 32;
    int c0 = blockIdx.y * 32;
    const float* src = feat    + (long long)b * CF * NS;
    float*       dst = g_featT + (long long)b * NS * CF;
#pragma unroll
    for (int r = 0; r < 4; ++r) {
        int c = c0 + threadIdx.y + r * 8;
        tile[threadIdx.y + r * 8][threadIdx.x] = src[c * NS + n0 + threadIdx.x];
    }
    __syncthreads();
#pragma unroll
    for (int r = 0; r < 4; ++r) {
        int n = n0 + threadIdx.y + r * 8;
        dst[n * CF + c0 + threadIdx.x] = tile[threadIdx.x][threadIdx.y + r * 8];
    }
}

// rotate+scale grid, write rel into X0[:, 0:3] and world query points into g_wq
__global__ void k_gridpoints(const float* __restrict__ center,
                             const float* __restrict__ size_,
                             const float* __restrict__ heading) {
    int m = blockIdx.x * blockDim.x + threadIdx.x;
    if (m >= M1) return;
    int g  = m & 63;
    int bk = m >> 6;  // b*K + k
    float sx = size_[bk * 3 + 0], sy = size_[bk * 3 + 1], sz = size_[bk * 3 + 2];
    float h  = heading[bk];
    float ch = cosf(h), sh = sinf(h);
    // linspace(-1,1,4): -1 + i*(2/3); x varies slowest
    float gx = -1.f + (float)( g >> 4      ) * (2.f / 3.f);
    float gy = -1.f + (float)((g >> 2) & 3 ) * (2.f / 3.f);
    float gz = -1.f + (float)( g       & 3 ) * (2.f / 3.f);
    float ax = gx * sx, ay = gy * sy, az = gz * sz;
    float rx = ax * ch - ay * sh;
    float ry = ax * sh + ay * ch;
    float rz = az;
    float* row = g_X0 + (long long)m * LDA0;
    row[0] = rx; row[1] = ry; row[2] = rz;
    g_wq[m * 3 + 0] = rx + center[bk * 3 + 0];
    g_wq[m * 3 + 1] = ry + center[bk * 3 + 1];
    g_wq[m * 3 + 2] = rz + center[bk * 3 + 2];
}

// 3-NN per query over 1024 seeds (seeds cached in SMEM), inverse-distance weights
__global__ void k_threenn(const float* __restrict__ seed_xyz) {
    __shared__ float4 sp[NS];
    int b = blockIdx.x >> 7;                       // 128 blocks per batch
    int q = ((blockIdx.x & 127) << 7) + threadIdx.x;
    for (int i = threadIdx.x; i < NS; i += blockDim.x) {
        float x = seed_xyz[((long long)b * NS + i) * 3 + 0];
        float y = seed_xyz[((long long)b * NS + i) * 3 + 1];
        float z = seed_xyz[((long long)b * NS + i) * 3 + 2];
        sp[i] = make_float4(x, y, z, x * x + y * y + z * z);
    }
    __syncthreads();
    int m = b * QQ + q;
    float qx = g_wq[m * 3 + 0], qy = g_wq[m * 3 + 1], qz = g_wq[m * 3 + 2];
    float qq = qx * qx + qy * qy + qz * qz;
    float d0 = 1e30f, d1 = 1e30f, d2 = 1e30f;
    int   i0 = 0, i1 = 0, i2 = 0;
    for (int n = 0; n < NS; ++n) {
        float4 p = sp[n];
        // expanded form, matching the reference's selection metric
        float d = qq + p.w - 2.f * (qx * p.x + qy * p.y + qz * p.z);
        if (d < d2) {
            if (d < d1) {
                d2 = d1; i2 = i1;
                if (d < d0) { d1 = d0; i1 = i0; d0 = d; i0 = n; }
                else        { d1 = d;  i1 = n; }
            } else { d2 = d; i2 = n; }
        }
    }
    int ii[3] = {i0, i1, i2};
    float w[3];
#pragma unroll
    for (int j = 0; j < 3; ++j) {
        float4 p = sp[ii[j]];
        float dx = p.x - qx, dy = p.y - qy, dz = p.z - qz;   // direct form, as reference
        float dist = sqrtf(dx * dx + dy * dy + dz * dz);
        w[j] = 1.f / (dist + 1e-8f);
    }
    float inv = 1.f / (w[0] + w[1] + w[2]);
#pragma unroll
    for (int j = 0; j < 3; ++j) {
        g_idx3[m * 3 + j] = ii[j];
        g_w3[m * 3 + j]   = w[j] * inv;
    }
}

// weighted feature gather: one warp per query, coalesced rows of g_featT
__global__ void k_interp() {
    int warp = (blockIdx.x * blockDim.x + threadIdx.x) >> 5;
    int lane = threadIdx.x & 31;
    int m = warp;
    int b = m >> 14;  // / 16384
    int i0 = g_idx3[m * 3 + 0], i1 = g_idx3[m * 3 + 1], i2 = g_idx3[m * 3 + 2];
    float w0 = g_w3[m * 3 + 0], w1 = g_w3[m * 3 + 1], w2 = g_w3[m * 3 + 2];
    const float* f0 = g_featT + ((long long)b * NS + i0) * CF;
    const float* f1 = g_featT + ((long long)b * NS + i1) * CF;
    const float* f2 = g_featT + ((long long)b * NS + i2) * CF;
    float* dst = g_X0 + (long long)m * LDA0 + 3;
#pragma unroll
    for (int c = lane; c < CF; c += 32)
        dst[c] = w0 * f0[c] + w1 * f1[c] + w2 * f2[c];
}

// C[m,n] = sum_k act(A[m,k]) * W[n,k] + bias[n]
// act = identity, or fused BN(scale/shift)+ReLU of the previous layer (BNA=true).
template <int KDIM, bool BNA>
__global__ void __launch_bounds__(256)
k_gemm(const float* __restrict__ A, int lda,
       const float* __restrict__ W,
       const float* __restrict__ bias,
       const float* __restrict__ scl,
       const float* __restrict__ shf,
       float* __restrict__ C) {
    __shared__ float As[16][128];
    __shared__ float Ws[16][128];
    int tid = threadIdx.x;
    int bm  = blockIdx.x * 128;
    int tx  = tid & 15, ty = tid >> 4;
    float acc[8][8];
#pragma unroll
    for (int i = 0; i < 8; ++i)
#pragma unroll
        for (int j = 0; j < 8; ++j) acc[i][j] = 0.f;

    const int KT = (KDIM + 15) / 16;
    for (int kt = 0; kt < KT; ++kt) {
        int k0 = kt * 16;
        // A tile (transposed into SMEM), 64B-contiguous per 4 lanes
#pragma unroll
        for (int r = 0; r < 2; ++r) {
            int row = (tid >> 2) + r * 64;
            int kv  = (tid & 3) * 4;
            int k   = k0 + kv;
            float4 v;
            if ((KDIM & 15) == 0 || k + 4 <= KDIM) {
                v = *reinterpret_cast<const float4*>(A + (long long)(bm + row) * lda + k);
            } else {
                const float* ap = A + (long long)(bm + row) * lda;
                v.x = (k + 0 < KDIM) ? ap[k + 0] : 0.f;
                v.y = (k + 1 < KDIM) ? ap[k + 1] : 0.f;
                v.z = (k + 2 < KDIM) ? ap[k + 2] : 0.f;
                v.w = (k + 3 < KDIM) ? ap[k + 3] : 0.f;
            }
            if (BNA) {  // KDIM==128 for all BNA instantiations -> always in-bounds
                v.x = fmaxf(v.x * scl[k + 0] + shf[k + 0], 0.f);
                v.y = fmaxf(v.y * scl[k + 1] + shf[k + 1], 0.f);
                v.z = fmaxf(v.z * scl[k + 2] + shf[k + 2], 0.f);
                v.w = fmaxf(v.w * scl[k + 3] + shf[k + 3], 0.f);
            }
            As[kv + 0][row] = v.x;
            As[kv + 1][row] = v.y;
            As[kv + 2][row] = v.z;
            As[kv + 3][row] = v.w;
        }
        // W tile: W[n][k], row-major [128, KDIM]
        {
            int n  = tid >> 1;
            int kb = (tid & 1) * 8;
#pragma unroll
            for (int i = 0; i < 8; ++i) {
                int k = k0 + kb + i;
                Ws[kb + i][n] = (k < KDIM) ? W[n * KDIM + k] : 0.f;
            }
        }
        __syncthreads();
#pragma unroll
        for (int kk = 0; kk < 16; ++kk) {
            float a[8], w8[8];
            *reinterpret_cast<float4*>(&a[0])  = *reinterpret_cast<const float4*>(&As[kk][ty * 8]);
            *reinterpret_cast<float4*>(&a[4])  = *reinterpret_cast<const float4*>(&As[kk][ty * 8 + 4]);
            *reinterpret_cast<float4*>(&w8[0]) = *reinterpret_cast<const float4*>(&Ws[kk][tx * 8]);
            *reinterpret_cast<float4*>(&w8[4]) = *reinterpret_cast<const float4*>(&Ws[kk][tx * 8 + 4]);
#pragma unroll
            for (int i = 0; i < 8; ++i)
#pragma unroll
                for (int j = 0; j < 8; ++j) acc[i][j] += a[i] * w8[j];
        }
        __syncthreads();
    }
    float bv[8];
#pragma unroll
    for (int j = 0; j < 8; ++j) bv[j] = bias[tx * 8 + j];
#pragma unroll
    for (int i = 0; i < 8; ++i) {
        long long off = (long long)(bm + ty * 8 + i) * 128 + tx * 8;
        float4 o0 = make_float4(acc[i][0] + bv[0], acc[i][1] + bv[1],
                                acc[i][2] + bv[2], acc[i][3] + bv[3]);
        float4 o1 = make_float4(acc[i][4] + bv[4], acc[i][5] + bv[5],
                                acc[i][6] + bv[6], acc[i][7] + bv[7]);
        *reinterpret_cast<float4*>(C + off)     = o0;
        *reinterpret_cast<float4*>(C + off + 4) = o1;
    }
}

// deterministic two-stage BN stats: per-block partial sums -> g_part
__global__ void k_stats(const float* __restrict__ Y, int M) {
    __shared__ float ss[256], sq[256];
    int c    = threadIdx.x & 127;
    int half = threadIdx.x >> 7;
    int rowsPer = M / gridDim.x;
    int r0 = blockIdx.x * rowsPer;
    float s = 0.f, s2 = 0.f;
    for (int r = r0 + half; r < r0 + rowsPer; r += 2) {
        float v = Y[(long long)r * 128 + c];
        s += v; s2 += v * v;
    }
    ss[threadIdx.x] = s; sq[threadIdx.x] = s2;
    __syncthreads();
    if (threadIdx.x < 128) {
        g_part[blockIdx.x * 256 + threadIdx.x]       = ss[threadIdx.x] + ss[threadIdx.x + 128];
        g_part[blockIdx.x * 256 + 128 + threadIdx.x] = sq[threadIdx.x] + sq[threadIdx.x + 128];
    }
}

// finalize: mean/var -> folded (scale, shift) for channel-wise BN
__global__ void k_bnfin(int NB, float Minv,
                        const float* __restrict__ gamma,
                        const float* __restrict__ beta,
                        int slot) {
    int c = threadIdx.x;
    float s = 0.f, s2 = 0.f;
    for (int b = 0; b < NB; ++b) {
        s  += g_part[b * 256 + c];
        s2 += g_part[b * 256 + 128 + c];
    }
    float mean = s * Minv;
    float var  = s2 * Minv - mean * mean;
    float rstd = rsqrtf(var + 1e-5f);
    float sc   = gamma[c] * rstd;
    g_scale[slot * 128 + c] = sc;
    g_shift[slot * 128 + c] = beta[c] - mean * sc;
}

// BN3 + ReLU + maxpool over the 64 grid points -> g_F [1024, 128]
__global__ void k_maxpool() {
    int bk = blockIdx.x;
    int c  = threadIdx.x;
    float sc = g_scale[2 * 128 + c], sf = g_shift[2 * 128 + c];
    const float* base = g_Y3 + (long long)bk * 64 * 128 + c;
    float mx = -1e30f;
#pragma unroll 4
    for (int g = 0; g < 64; ++g) {
        float v = base[g * 128] * sc + sf;
        mx = fmaxf(mx, v);
    }
    g_F[bk * 128 + c] = fmaxf(mx, 0.f);   // relu-then-max == max-then-relu
}

// BN5+ReLU on N2, project to the last 18 of 77 output channels
__global__ void k_final(const float* __restrict__ cw3,
                        const float* __restrict__ cb3,
                        float* __restrict__ out) {
    int t = blockIdx.x * blockDim.x + threadIdx.x;
    if (t >= MFC * IOUS) return;
    int j   = t % IOUS;
    int row = t / IOUS;
    int o   = (OUTC - IOUS) + j;   // 59 + j
    const float* wrow = cw3 + o * 128;
    const float* x    = g_N2 + row * 128;
    float acc = cb3[o];
#pragma unroll 8
    for (int i = 0; i < 128; ++i) {
        float v = fmaxf(x[i] * g_scale[4 * 128 + i] + g_shift[4 * 128 + i], 0.f);
        acc += v * wrow[i];
    }
    out[t] = acc;   // [B, K, 18] row-major since row = b*K + k
}

// ---------------- launcher ----------------
extern "C" void kernel_launch(void* const* d_in, const int* in_sizes, int n_in,
                              void* d_out, int out_size) {
    const float* center  = (const float*)d_in[0];
    const float* size_   = (const float*)d_in[1];
    const float* heading = (const float*)d_in[2];
    const float* sxyz    = (const float*)d_in[3];
    const float* sfeat   = (const float*)d_in[4];
    const float* w0  = (const float*)d_in[5];
    const float* b0  = (const float*)d_in[6];
    const float* g0  = (const float*)d_in[7];
    const float* be0 = (const float*)d_in[8];
    const float* w1  = (const float*)d_in[9];
    const float* b1  = (const float*)d_in[10];
    const float* g1  = (const float*)d_in[11];
    const float* be1 = (const float*)d_in[12];
    const float* w2  = (const float*)d_in[13];
    const float* b2  = (const float*)d_in[14];
    const float* g2  = (const float*)d_in[15];
    const float* be2 = (const float*)d_in[16];
    const float* cw1 = (const float*)d_in[17];
    const float* cb1 = (const float*)d_in[18];
    const float* g3  = (const float*)d_in[19];
    const float* be3 = (const float*)d_in[20];
    const float* cw2 = (const float*)d_in[21];
    const float* cb2 = (const float*)d_in[22];
    const float* g4  = (const float*)d_in[23];
    const float* be4 = (const float*)d_in[24];
    const float* cw3 = (const float*)d_in[25];
    const float* cb3 = (const float*)d_in[26];
    float* out = (float*)d_out;

    void *pX0, *pY1, *pY2, *pY3, *pF, *pN1, *pN2, *pSC, *pSH;
    cudaGetSymbolAddress(&pX0, g_X0);
    cudaGetSymbolAddress(&pY1, g_Y1);
    cudaGetSymbolAddress(&pY2, g_Y2);
    cudaGetSymbolAddress(&pY3, g_Y3);
    cudaGetSymbolAddress(&pF,  g_F);
    cudaGetSymbolAddress(&pN1, g_N1);
    cudaGetSymbolAddress(&pN2, g_N2);
    cudaGetSymbolAddress(&pSC, g_scale);
    cudaGetSymbolAddress(&pSH, g_shift);
    float* X0 = (float*)pX0;
    float* Y1 = (float*)pY1;
    float* Y2 = (float*)pY2;
    float* Y3 = (float*)pY3;
    float* F  = (float*)pF;
    float* N1 = (float*)pN1;
    float* N2 = (float*)pN2;
    float* SC = (float*)pSC;
    float* SH = (float*)pSH;

    // stage 1: geometry + interpolation inputs
    k_transpose<<<dim3(NS / 32, CF / 32, BB), dim3(32, 8)>>>(sfeat);
    k_gridpoints<<<M1 / 256, 256>>>(center, size_, heading);
    k_threenn<<<BB * 128, 128>>>(sxyz);
    k_interp<<<M1 / 8, 256>>>();

    // stage 2: SharedMLP (GEMM + training BN folded into next layer's load)
    k_gemm<CIN0, false><<<M1 / 128, 256>>>(X0, LDA0, w0, b0, nullptr, nullptr, Y1);
    k_stats<<<128, 256>>>(Y1, M1);
    k_bnfin<<<1, 128>>>(128, 1.f / M1, g0, be0, 0);

    k_gemm<HH, true><<<M1 / 128, 256>>>(Y1, HH, w1, b1, SC + 0 * 128, SH + 0 * 128, Y2);
    k_stats<<<128, 256>>>(Y2, M1);
    k_bnfin<<<1, 128>>>(128, 1.f / M1, g1, be1, 1);

    k_gemm<HH, true><<<M1 / 128, 256>>>(Y2, HH, w2, b2, SC + 1 * 128, SH + 1 * 128, Y3);
    k_stats<<<128, 256>>>(Y3, M1);
    k_bnfin<<<1, 128>>>(128, 1.f / M1, g2, be2, 2);

    // stage 3: pool + FC head
    k_maxpool<<<MFC, 128>>>();

    k_gemm<HH, false><<<MFC / 128, 256>>>(F, HH, cw1, cb1, nullptr, nullptr, N1);
    k_stats<<<8, 256>>>(N1, MFC);
    k_bnfin<<<1, 128>>>(8, 1.f / MFC, g3, be3, 3);

    k_gemm<HH, true><<<MFC / 128, 256>>>(N1, HH, cw2, cb2, SC + 3 * 128, SH + 3 * 128, N2);
    k_stats<<<8, 256>>>(N2, MFC);
    k_bnfin<<<1, 128>>>(8, 1.f / MFC, g4, be4, 4);

    k_final<<<(MFC * IOUS + 255) / 256, 256>>>(cw3, cb3, out);
}

// round 3
// speedup vs baseline: 1.1525x; 1.1525x over previous
#include <cuda_runtime.h>
#include <math.h>
#include <stdint.h>

// ---------------- problem constants ----------------
static constexpr int BB   = 4;
static constexpr int KK   = 256;
static constexpr int NS   = 1024;      // seeds
static constexpr int CF   = 256;       // seed feature channels
static constexpr int GPP  = 64;        // grid points per proposal
static constexpr int QQ   = KK * GPP;  // 16384 queries per batch
static constexpr int M1   = BB * QQ;   // 65536 rows for conv layers
static constexpr int CIN0 = CF + 3;    // 259 logical input channels
static constexpr int LDA0 = 288;       // padded phys leading dim for X0 (18 k-chunks of 16)
static constexpr int HH   = 128;
static constexpr int MFC  = BB * KK;   // 1024 rows for FC layers
static constexpr int IOUS = 18;
static constexpr int OUTC = 77;

// X0 physical layout: cols [0,256) = interp features, [256,259) = rel xyz, [259,288) pad.
// Layer-0 W load permutes: phys k<256 -> logical k+3 ; phys 256..258 -> logical k-256.

// ---------------- scratch (static device memory; no allocations) ----------------
__device__ float g_X0[(long long)M1 * LDA0];
__device__ float g_wq[M1 * 3];
__device__ float g_featT[BB * NS * CF];        // [b][n][c]
__device__ int   g_idx3[M1 * 3];
__device__ float g_w3[M1 * 3];
__device__ float g_Y1[(long long)M1 * HH];
__device__ float g_Y2[(long long)M1 * HH];
__device__ float g_Y3[(long long)M1 * HH];
__device__ float g_F [MFC * HH];
__device__ float g_N1[MFC * HH];
__device__ float g_N2[MFC * HH];
__device__ float g_part[128 * 256];
__device__ float g_scale[5 * 128];
__device__ float g_shift[5 * 128];

// ---------------- small helpers ----------------
__device__ __forceinline__ uint32_t f2tf32(float x) {
    uint32_t r;
    asm("cvt.rna.tf32.f32 %0, %1;" : "=r"(r) : "f"(x));
    return r;
}

// split x into tf32 hi + tf32 lo (3xTF32 trick)
__device__ __forceinline__ void split_tf32(float x, uint32_t& hi, uint32_t& lo) {
    hi = f2tf32(x);
    lo = f2tf32(x - __uint_as_float(hi));
}

__device__ __forceinline__ void mma_tf32(float& c0, float& c1, float& c2, float& c3,
                                         uint32_t a0, uint32_t a1, uint32_t a2, uint32_t a3,
                                         uint32_t b0, uint32_t b1) {
    asm volatile(
        "mma.sync.aligned.m16n8k8.row.col.f32.tf32.tf32.f32 "
        "{%0,%1,%2,%3}, {%4,%5,%6,%7}, {%8,%9}, {%0,%1,%2,%3};"
        : "+f"(c0), "+f"(c1), "+f"(c2), "+f"(c3)
        : "r"(a0), "r"(a1), "r"(a2), "r"(a3), "r"(b0), "r"(b1));
}

// ---------------- kernels ----------------

// seed_features [b][c][n] -> g_featT [b][n][c]
__global__ void k_transpose(const float* __restrict__ feat) {
    __shared__ float tile[32][33];
    int b  = blockIdx.z;
    int n0 = blockIdx.x * 32;
    int c0 = blockIdx.y * 32;
    const float* src = feat    + (long long)b * CF * NS;
    float*       dst = g_featT + (long long)b * NS * CF;
#pragma unroll
    for (int r = 0; r < 4; ++r) {
        int c = c0 + threadIdx.y + r * 8;
        tile[threadIdx.y + r * 8][threadIdx.x] = src[c * NS + n0 + threadIdx.x];
    }
    __syncthreads();
#pragma unroll
    for (int r = 0; r < 4; ++r) {
        int n = n0 + threadIdx.y + r * 8;
        dst[n * CF + c0 + threadIdx.x] = tile[threadIdx.x][threadIdx.y + r * 8];
    }
}

// rotate+scale grid, write rel into X0[:, 256:259] and world query points into g_wq
__global__ void k_gridpoints(const float* __restrict__ center,
                             const float* __restrict__ size_,
                             const float* __restrict__ heading) {
    int m = blockIdx.x * blockDim.x + threadIdx.x;
    if (m >= M1) return;
    int g  = m & 63;
    int bk = m >> 6;
    float sx = size_[bk * 3 + 0], sy = size_[bk * 3 + 1], sz = size_[bk * 3 + 2];
    float h  = heading[bk];
    float ch = cosf(h), sh = sinf(h);
    float gx = -1.f + (float)( g >> 4      ) * (2.f / 3.f);
    float gy = -1.f + (float)((g >> 2) & 3 ) * (2.f / 3.f);
    float gz = -1.f + (float)( g       & 3 ) * (2.f / 3.f);
    float ax = gx * sx, ay = gy * sy, az = gz * sz;
    float rx = ax * ch - ay * sh;
    float ry = ax * sh + ay * ch;
    float rz = az;
    float* row = g_X0 + (long long)m * LDA0;
    row[256] = rx; row[257] = ry; row[258] = rz;
    g_wq[m * 3 + 0] = rx + center[bk * 3 + 0];
    g_wq[m * 3 + 1] = ry + center[bk * 3 + 1];
    g_wq[m * 3 + 2] = rz + center[bk * 3 + 2];
}

// 3-NN per query over 1024 seeds (seeds cached in SMEM), inverse-distance weights
__global__ void k_threenn(const float* __restrict__ seed_xyz) {
    __shared__ float4 sp[NS];
    int b = blockIdx.x >> 7;
    int q = ((blockIdx.x & 127) << 7) + threadIdx.x;
    for (int i = threadIdx.x; i < NS; i += blockDim.x) {
        float x = seed_xyz[((long long)b * NS + i) * 3 + 0];
        float y = seed_xyz[((long long)b * NS + i) * 3 + 1];
        float z = seed_xyz[((long long)b * NS + i) * 3 + 2];
        sp[i] = make_float4(x, y, z, x * x + y * y + z * z);
    }
    __syncthreads();
    int m = b * QQ + q;
    float qx = g_wq[m * 3 + 0], qy = g_wq[m * 3 + 1], qz = g_wq[m * 3 + 2];
    float qq = qx * qx + qy * qy + qz * qz;
    float d0 = 1e30f, d1 = 1e30f, d2 = 1e30f;
    int   i0 = 0, i1 = 0, i2 = 0;
    for (int n = 0; n < NS; ++n) {
        float4 p = sp[n];
        float d = qq + p.w - 2.f * (qx * p.x + qy * p.y + qz * p.z);
        if (d < d2) {
            if (d < d1) {
                d2 = d1; i2 = i1;
                if (d < d0) { d1 = d0; i1 = i0; d0 = d; i0 = n; }
                else        { d1 = d;  i1 = n; }
            } else { d2 = d; i2 = n; }
        }
    }
    int ii[3] = {i0, i1, i2};
    float w[3];
#pragma unroll
    for (int j = 0; j < 3; ++j) {
        float4 p = sp[ii[j]];
        float dx = p.x - qx, dy = p.y - qy, dz = p.z - qz;
        float dist = sqrtf(dx * dx + dy * dy + dz * dz);
        w[j] = 1.f / (dist + 1e-8f);
    }
    float inv = 1.f / (w[0] + w[1] + w[2]);
#pragma unroll
    for (int j = 0; j < 3; ++j) {
        g_idx3[m * 3 + j] = ii[j];
        g_w3[m * 3 + j]   = w[j] * inv;
    }
}

// weighted feature gather: one warp per query, float4 rows of g_featT -> X0[:,0:256)
__global__ void k_interp() {
    int warp = (blockIdx.x * blockDim.x + threadIdx.x) >> 5;
    int lane = threadIdx.x & 31;
    int m = warp;
    int b = m >> 14;
    int i0 = g_idx3[m * 3 + 0], i1 = g_idx3[m * 3 + 1], i2 = g_idx3[m * 3 + 2];
    float w0 = g_w3[m * 3 + 0], w1 = g_w3[m * 3 + 1], w2 = g_w3[m * 3 + 2];
    const float4* f0 = (const float4*)(g_featT + ((long long)b * NS + i0) * CF);
    const float4* f1 = (const float4*)(g_featT + ((long long)b * NS + i1) * CF);
    const float4* f2 = (const float4*)(g_featT + ((long long)b * NS + i2) * CF);
    float4* dst = (float4*)(g_X0 + (long long)m * LDA0);
#pragma unroll
    for (int c = lane; c < CF / 4; c += 32) {
        float4 a = f0[c], bq = f1[c], cq = f2[c];
        dst[c] = make_float4(w0 * a.x + w1 * bq.x + w2 * cq.x,
                             w0 * a.y + w1 * bq.y + w2 * cq.y,
                             w0 * a.z + w1 * bq.z + w2 * cq.z,
                             w0 * a.w + w1 * bq.w + w2 * cq.w);
    }
}

// -------- 3xTF32 tensor-core GEMM: C[m,n] = sum_k act(A[m,k]) * W[n,k] + bias[n] --------
// 128x128 tile, K-chunks of 16. 8 warps (2 over M x 4 over N), warp tile 64x32.
// Split precision: hi/lo tf32 tiles, acc += hi*hi + lo*hi + hi*lo (fp32-accurate).
// act = identity, or fused BN(scale/shift)+ReLU of previous layer when BNA.
// PERM: layer-0 column permutation of W (X0 is stored interp-first).
template <int KDIM, bool BNA, bool PERM>
__global__ void __launch_bounds__(256)
k_gemm_tc(const float* __restrict__ A, int lda,
          const float* __restrict__ W,
          const float* __restrict__ bias,
          const float* __restrict__ scl,
          const float* __restrict__ shf,
          float* __restrict__ C) {
    __shared__ uint32_t AsH[16][136];
    __shared__ uint32_t AsL[16][136];
    __shared__ uint32_t WsH[16][136];
    __shared__ uint32_t WsL[16][136];
    const int tid  = threadIdx.x;
    const int lane = tid & 31;
    const int warp = tid >> 5;
    const int g    = lane >> 2;        // 0..7
    const int q    = lane & 3;         // 0..3
    const int wm   = warp & 1;         // 2 warps over M
    const int wn   = warp >> 1;        // 4 warps over N
    const int bm   = blockIdx.x * 128;

    float acc[4][4][4];
#pragma unroll
    for (int i = 0; i < 4; ++i)
#pragma unroll
        for (int j = 0; j < 4; ++j)
#pragma unroll
            for (int r = 0; r < 4; ++r) acc[i][j][r] = 0.f;

    const int ldrow = tid >> 1;        // 0..127
    const int ldkv  = (tid & 1) * 8;   // 0 or 8
    const int NCH   = (KDIM + 15) / 16;

    for (int ch = 0; ch < NCH; ++ch) {
        const int k0 = ch * 16;
        // ---- A tile -> AsH/AsL[k][m] ----
        {
            const float* ap = A + (long long)(bm + ldrow) * lda + k0 + ldkv;
            float4 u0 = *(const float4*)(ap + 0);
            float4 u1 = *(const float4*)(ap + 4);
            float v[8] = {u0.x, u0.y, u0.z, u0.w, u1.x, u1.y, u1.z, u1.w};
            if (PERM) {
#pragma unroll
                for (int i = 0; i < 8; ++i)
                    if (k0 + ldkv + i >= KDIM) v[i] = 0.f;   // pad cols are garbage
            }
            if (BNA) {
#pragma unroll
                for (int i = 0; i < 8; ++i) {
                    int k = k0 + ldkv + i;   // BNA only with KDIM=128: always valid
                    v[i] = fmaxf(v[i] * scl[k] + shf[k], 0.f);
                }
            }
#pragma unroll
            for (int i = 0; i < 8; ++i) {
                uint32_t hi, lo;
                split_tf32(v[i], hi, lo);
                AsH[ldkv + i][ldrow] = hi;
                AsL[ldkv + i][ldrow] = lo;
            }
        }
        // ---- W tile -> WsH/WsL[k][n] ----
        {
            const int n = ldrow;
            float v[8];
            if (PERM) {
#pragma unroll
                for (int i = 0; i < 8; ++i) {
                    int k = k0 + ldkv + i;
                    v[i] = 0.f;
                    if (k < KDIM) {
                        int kl = (k < 256) ? (k + 3) : (k - 256);
                        v[i] = W[n * KDIM + kl];
                    }
                }
            } else {
                const float* wp = W + (long long)n * KDIM + k0 + ldkv;
                float4 u0 = *(const float4*)(wp + 0);
                float4 u1 = *(const float4*)(wp + 4);
                v[0]=u0.x; v[1]=u0.y; v[2]=u0.z; v[3]=u0.w;
                v[4]=u1.x; v[5]=u1.y; v[6]=u1.z; v[7]=u1.w;
            }
#pragma unroll
            for (int i = 0; i < 8; ++i) {
                uint32_t hi, lo;
                split_tf32(v[i], hi, lo);
                WsH[ldkv + i][n] = hi;
                WsL[ldkv + i][n] = lo;
            }
        }
        __syncthreads();

#pragma unroll
        for (int kk = 0; kk < 16; kk += 8) {
            uint32_t aH[4][4], aL[4][4], bH[4][2], bL[4][2];
#pragma unroll
            for (int mt = 0; mt < 4; ++mt) {
                int mbase = wm * 64 + mt * 16;
                aH[mt][0] = AsH[kk + q    ][mbase + g    ];
                aH[mt][1] = AsH[kk + q    ][mbase + g + 8];
                aH[mt][2] = AsH[kk + q + 4][mbase + g    ];
                aH[mt][3] = AsH[kk + q + 4][mbase + g + 8];
                aL[mt][0] = AsL[kk + q    ][mbase + g    ];
                aL[mt][1] = AsL[kk + q    ][mbase + g + 8];
                aL[mt][2] = AsL[kk + q + 4][mbase + g    ];
                aL[mt][3] = AsL[kk + q + 4][mbase + g + 8];
            }
#pragma unroll
            for (int nt = 0; nt < 4; ++nt) {
                int nbase = wn * 32 + nt * 8;
                bH[nt][0] = WsH[kk + q    ][nbase + g];
                bH[nt][1] = WsH[kk + q + 4][nbase + g];
                bL[nt][0] = WsL[kk + q    ][nbase + g];
                bL[nt][1] = WsL[kk + q + 4][nbase + g];
            }
#pragma unroll
            for (int mt = 0; mt < 4; ++mt)
#pragma unroll
                for (int nt = 0; nt < 4; ++nt) {
                    // lo terms first, hi*hi last (accumulate small -> large)
                    mma_tf32(acc[mt][nt][0], acc[mt][nt][1], acc[mt][nt][2], acc[mt][nt][3],
                             aL[mt][0], aL[mt][1], aL[mt][2], aL[mt][3],
                             bH[nt][0], bH[nt][1]);
                    mma_tf32(acc[mt][nt][0], acc[mt][nt][1], acc[mt][nt][2], acc[mt][nt][3],
                             aH[mt][0], aH[mt][1], aH[mt][2], aH[mt][3],
                             bL[nt][0], bL[nt][1]);
                    mma_tf32(acc[mt][nt][0], acc[mt][nt][1], acc[mt][nt][2], acc[mt][nt][3],
                             aH[mt][0], aH[mt][1], aH[mt][2], aH[mt][3],
                             bH[nt][0], bH[nt][1]);
                }
        }
        __syncthreads();
    }

    // ---- epilogue: bias + store ----
#pragma unroll
    for (int nt = 0; nt < 4; ++nt) {
        int col = wn * 32 + nt * 8 + q * 2;
        float bx = bias[col], by = bias[col + 1];
#pragma unroll
        for (int mt = 0; mt < 4; ++mt) {
            int r0 = bm + wm * 64 + mt * 16 + g;
            float2 o0 = make_float2(acc[mt][nt][0] + bx, acc[mt][nt][1] + by);
            float2 o1 = make_float2(acc[mt][nt][2] + bx, acc[mt][nt][3] + by);
            *(float2*)(C + (long long)r0 * 128 + col)       = o0;
            *(float2*)(C + (long long)(r0 + 8) * 128 + col) = o1;
        }
    }
}

// -------- fp32 SIMT GEMM kept for the tiny FC layers (M=1024) --------
template <int KDIM, bool BNA>
__global__ void __launch_bounds__(256)
k_gemm(const float* __restrict__ A, int lda,
       const float* __restrict__ W,
       const float* __restrict__ bias,
       const float* __restrict__ scl,
       const float* __restrict__ shf,
       float* __restrict__ C) {
    __shared__ float As[16][128];
    __shared__ float Ws2[16][128];
    int tid = threadIdx.x;
    int bm  = blockIdx.x * 128;
    int tx  = tid & 15, ty = tid >> 4;
    float acc[8][8];
#pragma unroll
    for (int i = 0; i < 8; ++i)
#pragma unroll
        for (int j = 0; j < 8; ++j) acc[i][j] = 0.f;

    const int KT = (KDIM + 15) / 16;
    for (int kt = 0; kt < KT; ++kt) {
        int k0 = kt * 16;
#pragma unroll
        for (int r = 0; r < 2; ++r) {
            int row = (tid >> 2) + r * 64;
            int kv  = (tid & 3) * 4;
            int k   = k0 + kv;
            float4 v = *reinterpret_cast<const float4*>(A + (long long)(bm + row) * lda + k);
            if (BNA) {
                v.x = fmaxf(v.x * scl[k + 0] + shf[k + 0], 0.f);
                v.y = fmaxf(v.y * scl[k + 1] + shf[k + 1], 0.f);
                v.z = fmaxf(v.z * scl[k + 2] + shf[k + 2], 0.f);
                v.w = fmaxf(v.w * scl[k + 3] + shf[k + 3], 0.f);
            }
            As[kv + 0][row] = v.x;
            As[kv + 1][row] = v.y;
            As[kv + 2][row] = v.z;
            As[kv + 3][row] = v.w;
        }
        {
            int n  = tid >> 1;
            int kb = (tid & 1) * 8;
#pragma unroll
            for (int i = 0; i < 8; ++i) {
                int k = k0 + kb + i;
                Ws2[kb + i][n] = W[n * KDIM + k];
            }
        }
        __syncthreads();
#pragma unroll
        for (int kk = 0; kk < 16; ++kk) {
            float a[8], w8[8];
            *reinterpret_cast<float4*>(&a[0])  = *reinterpret_cast<const float4*>(&As[kk][ty * 8]);
            *reinterpret_cast<float4*>(&a[4])  = *reinterpret_cast<const float4*>(&As[kk][ty * 8 + 4]);
            *reinterpret_cast<float4*>(&w8[0]) = *reinterpret_cast<const float4*>(&Ws2[kk][tx * 8]);
            *reinterpret_cast<float4*>(&w8[4]) = *reinterpret_cast<const float4*>(&Ws2[kk][tx * 8 + 4]);
#pragma unroll
            for (int i = 0; i < 8; ++i)
#pragma unroll
                for (int j = 0; j < 8; ++j) acc[i][j] += a[i] * w8[j];
        }
        __syncthreads();
    }
    float bv[8];
#pragma unroll
    for (int j = 0; j < 8; ++j) bv[j] = bias[tx * 8 + j];
#pragma unroll
    for (int i = 0; i < 8; ++i) {
        long long off = (long long)(bm + ty * 8 + i) * 128 + tx * 8;
        float4 o0 = make_float4(acc[i][0] + bv[0], acc[i][1] + bv[1],
                                acc[i][2] + bv[2], acc[i][3] + bv[3]);
        float4 o1 = make_float4(acc[i][4] + bv[4], acc[i][5] + bv[5],
                                acc[i][6] + bv[6], acc[i][7] + bv[7]);
        *reinterpret_cast<float4*>(C + off)     = o0;
        *reinterpret_cast<float4*>(C + off + 4) = o1;
    }
}

// deterministic two-stage BN stats: per-block partial sums -> g_part
__global__ void k_stats(const float* __restrict__ Y, int M) {
    __shared__ float ss[256], sq[256];
    int c    = threadIdx.x & 127;
    int half = threadIdx.x >> 7;
    int rowsPer = M / gridDim.x;
    int r0 = blockIdx.x * rowsPer;
    float s = 0.f, s2 = 0.f;
    for (int r = r0 + half; r < r0 + rowsPer; r += 2) {
        float v = Y[(long long)r * 128 + c];
        s += v; s2 += v * v;
    }
    ss[threadIdx.x] = s; sq[threadIdx.x] = s2;
    __syncthreads();
    if (threadIdx.x < 128) {
        g_part[blockIdx.x * 256 + threadIdx.x]       = ss[threadIdx.x] + ss[threadIdx.x + 128];
        g_part[blockIdx.x * 256 + 128 + threadIdx.x] = sq[threadIdx.x] + sq[threadIdx.x + 128];
    }
}

__global__ void k_bnfin(int NB, float Minv,
                        const float* __restrict__ gamma,
                        const float* __restrict__ beta,
                        int slot) {
    int c = threadIdx.x;
    float s = 0.f, s2 = 0.f;
    for (int b = 0; b < NB; ++b) {
        s  += g_part[b * 256 + c];
        s2 += g_part[b * 256 + 128 + c];
    }
    float mean = s * Minv;
    float var  = s2 * Minv - mean * mean;
    float rstd = rsqrtf(var + 1e-5f);
    float sc   = gamma[c] * rstd;
    g_scale[slot * 128 + c] = sc;
    g_shift[slot * 128 + c] = beta[c] - mean * sc;
}

// BN3 + ReLU + maxpool over the 64 grid points -> g_F [1024, 128]
__global__ void k_maxpool() {
    int bk = blockIdx.x;
    int c  = threadIdx.x;
    float sc = g_scale[2 * 128 + c], sf = g_shift[2 * 128 + c];
    const float* base = g_Y3 + (long long)bk * 64 * 128 + c;
    float mx = -1e30f;
#pragma unroll 4
    for (int g = 0; g < 64; ++g) {
        float v = base[g * 128] * sc + sf;
        mx = fmaxf(mx, v);
    }
    g_F[bk * 128 + c] = fmaxf(mx, 0.f);
}

// BN5+ReLU on N2, project to the last 18 of 77 output channels
__global__ void k_final(const float* __restrict__ cw3,
                        const float* __restrict__ cb3,
                        float* __restrict__ out) {
    int t = blockIdx.x * blockDim.x + threadIdx.x;
    if (t >= MFC * IOUS) return;
    int j   = t % IOUS;
    int row = t / IOUS;
    int o   = (OUTC - IOUS) + j;
    const float* wrow = cw3 + o * 128;
    const float* x    = g_N2 + row * 128;
    float acc = cb3[o];
#pragma unroll 8
    for (int i = 0; i < 128; ++i) {
        float v = fmaxf(x[i] * g_scale[4 * 128 + i] + g_shift[4 * 128 + i], 0.f);
        acc += v * wrow[i];
    }
    out[t] = acc;
}

// ---------------- launcher ----------------
extern "C" void kernel_launch(void* const* d_in, const int* in_sizes, int n_in,
                              void* d_out, int out_size) {
    const float* center  = (const float*)d_in[0];
    const float* size_   = (const float*)d_in[1];
    const float* heading = (const float*)d_in[2];
    const float* sxyz    = (const float*)d_in[3];
    const float* sfeat   = (const float*)d_in[4];
    const float* w0  = (const float*)d_in[5];
    const float* b0  = (const float*)d_in[6];
    const float* g0  = (const float*)d_in[7];
    const float* be0 = (const float*)d_in[8];
    const float* w1  = (const float*)d_in[9];
    const float* b1  = (const float*)d_in[10];
    const float* g1  = (const float*)d_in[11];
    const float* be1 = (const float*)d_in[12];
    const float* w2  = (const float*)d_in[13];
    const float* b2  = (const float*)d_in[14];
    const float* g2  = (const float*)d_in[15];
    const float* be2 = (const float*)d_in[16];
    const float* cw1 = (const float*)d_in[17];
    const float* cb1 = (const float*)d_in[18];
    const float* g3  = (const float*)d_in[19];
    const float* be3 = (const float*)d_in[20];
    const float* cw2 = (const float*)d_in[21];
    const float* cb2 = (const float*)d_in[22];
    const float* g4  = (const float*)d_in[23];
    const float* be4 = (const float*)d_in[24];
    const float* cw3 = (const float*)d_in[25];
    const float* cb3 = (const float*)d_in[26];
    float* out = (float*)d_out;

    void *pX0, *pY1, *pY2, *pY3, *pF, *pN1, *pN2, *pSC, *pSH;
    cudaGetSymbolAddress(&pX0, g_X0);
    cudaGetSymbolAddress(&pY1, g_Y1);
    cudaGetSymbolAddress(&pY2, g_Y2);
    cudaGetSymbolAddress(&pY3, g_Y3);
    cudaGetSymbolAddress(&pF,  g_F);
    cudaGetSymbolAddress(&pN1, g_N1);
    cudaGetSymbolAddress(&pN2, g_N2);
    cudaGetSymbolAddress(&pSC, g_scale);
    cudaGetSymbolAddress(&pSH, g_shift);
    float* X0 = (float*)pX0;
    float* Y1 = (float*)pY1;
    float* Y2 = (float*)pY2;
    float* Y3 = (float*)pY3;
    float* F  = (float*)pF;
    float* N1 = (float*)pN1;
    float* N2 = (float*)pN2;
    float* SC = (float*)pSC;
    float* SH = (float*)pSH;

    // stage 1: geometry + interpolation inputs
    k_transpose<<<dim3(NS / 32, CF / 32, BB), dim3(32, 8)>>>(sfeat);
    k_gridpoints<<<M1 / 256, 256>>>(center, size_, heading);
    k_threenn<<<BB * 128, 128>>>(sxyz);
    k_interp<<<M1 / 8, 256>>>();

    // stage 2: SharedMLP on tensor cores (3xTF32), training BN folded into next layer's load
    k_gemm_tc<CIN0, false, true><<<M1 / 128, 256>>>(X0, LDA0, w0, b0, nullptr, nullptr, Y1);
    k_stats<<<128, 256>>>(Y1, M1);
    k_bnfin<<<1, 128>>>(128, 1.f / M1, g0, be0, 0);

    k_gemm_tc<HH, true, false><<<M1 / 128, 256>>>(Y1, HH, w1, b1, SC + 0 * 128, SH + 0 * 128, Y2);
    k_stats<<<128, 256>>>(Y2, M1);
    k_bnfin<<<1, 128>>>(128, 1.f / M1, g1, be1, 1);

    k_gemm_tc<HH, true, false><<<M1 / 128, 256>>>(Y2, HH, w2, b2, SC + 1 * 128, SH + 1 * 128, Y3);
    k_stats<<<128, 256>>>(Y3, M1);
    k_bnfin<<<1, 128>>>(128, 1.f / M1, g2, be2, 2);

    // stage 3: pool + FC head (fp32, tiny)
    k_maxpool<<<MFC, 128>>>();

    k_gemm<HH, false><<<MFC / 128, 256>>>(F, HH, cw1, cb1, nullptr, nullptr, N1);
    k_stats<<<8, 256>>>(N1, MFC);
    k_bnfin<<<1, 128>>>(8, 1.f / MFC, g3, be3, 3);

    k_gemm<HH, true><<<MFC / 128, 256>>>(N1, HH, cw2, cb2, SC + 3 * 128, SH + 3 * 128, N2);
    k_stats<<<8, 256>>>(N2, MFC);
    k_bnfin<<<1, 128>>>(8, 1.f / MFC, g4, be4, 4);

    k_final<<<(MFC * IOUS + 255) / 256, 256>>>(cw3, cb3, out);
}

// round 4
// speedup vs baseline: 1.2910x; 1.1201x over previous
#include <cuda_runtime.h>
#include <cuda_bf16.h>
#include <math.h>
#include <stdint.h>

// ---------------- problem constants ----------------
static constexpr int BB   = 4;
static constexpr int KK   = 256;
static constexpr int NS   = 1024;      // seeds
static constexpr int CF   = 256;       // seed feature channels
static constexpr int GPP  = 64;        // grid points per proposal
static constexpr int QQ   = KK * GPP;  // 16384 queries per batch
static constexpr int M1   = BB * QQ;   // 65536 rows for conv layers
static constexpr int CIN0 = CF + 3;    // 259 logical input channels
static constexpr int LDA0 = 288;       // padded phys leading dim for X0 (9 k-chunks of 32)
static constexpr int HH   = 128;
static constexpr int MFC  = BB * KK;   // 1024 rows for FC layers
static constexpr int IOUS = 18;
static constexpr int OUTC = 77;

// X0 physical layout: cols [0,256) = interp features, [256,259) = rel xyz, [259,288) pad.
// Layer-0 W load permutes: phys k<256 -> logical k+3 ; phys 256..258 -> logical k-256.

// ---------------- scratch (static device memory; no allocations) ----------------
__device__ float g_X0[(long long)M1 * LDA0];
__device__ float g_wq[M1 * 3];
__device__ float g_featT[BB * NS * CF];        // [b][n][c]
__device__ int   g_idx3[M1 * 3];
__device__ float g_w3[M1 * 3];
__device__ float g_Y1[(long long)M1 * HH];
__device__ float g_Y2[(long long)M1 * HH];
__device__ float g_Y3[(long long)M1 * HH];
__device__ float g_F [MFC * HH];
__device__ float g_N1[MFC * HH];
__device__ float g_N2[MFC * HH];
__device__ float g_part[128 * 256];
__device__ float g_scale[5 * 128];
__device__ float g_shift[5 * 128];

// ---------------- small helpers ----------------
// split two fp32 values into packed-bf16 (hi pair, lo pair); word = {k_even, k_odd}
__device__ __forceinline__ void split2_bf16(float v0, float v1, uint32_t& hi, uint32_t& lo) {
    __nv_bfloat16 h0 = __float2bfloat16_rn(v0);
    __nv_bfloat16 h1 = __float2bfloat16_rn(v1);
    float l0 = v0 - __bfloat162float(h0);
    float l1 = v1 - __bfloat162float(h1);
    __nv_bfloat162 hp = __halves2bfloat162(h0, h1);
    __nv_bfloat162 lp = __floats2bfloat162_rn(l0, l1);
    hi = *reinterpret_cast<uint32_t*>(&hp);
    lo = *reinterpret_cast<uint32_t*>(&lp);
}

__device__ __forceinline__ void mma_bf16(float& c0, float& c1, float& c2, float& c3,
                                         uint32_t a0, uint32_t a1, uint32_t a2, uint32_t a3,
                                         uint32_t b0, uint32_t b1) {
    asm volatile(
        "mma.sync.aligned.m16n8k16.row.col.f32.bf16.bf16.f32 "
        "{%0,%1,%2,%3}, {%4,%5,%6,%7}, {%8,%9}, {%0,%1,%2,%3};"
        : "+f"(c0), "+f"(c1), "+f"(c2), "+f"(c3)
        : "r"(a0), "r"(a1), "r"(a2), "r"(a3), "r"(b0), "r"(b1));
}

// ---------------- kernels ----------------

// seed_features [b][c][n] -> g_featT [b][n][c]
__global__ void k_transpose(const float* __restrict__ feat) {
    __shared__ float tile[32][33];
    int b  = blockIdx.z;
    int n0 = blockIdx.x * 32;
    int c0 = blockIdx.y * 32;
    const float* src = feat    + (long long)b * CF * NS;
    float*       dst = g_featT + (long long)b * NS * CF;
#pragma unroll
    for (int r = 0; r < 4; ++r) {
        int c = c0 + threadIdx.y + r * 8;
        tile[threadIdx.y + r * 8][threadIdx.x] = src[c * NS + n0 + threadIdx.x];
    }
    __syncthreads();
#pragma unroll
    for (int r = 0; r < 4; ++r) {
        int n = n0 + threadIdx.y + r * 8;
        dst[n * CF + c0 + threadIdx.x] = tile[threadIdx.x][threadIdx.y + r * 8];
    }
}

// rotate+scale grid, write rel into X0[:, 256:259] and world query points into g_wq
__global__ void k_gridpoints(const float* __restrict__ center,
                             const float* __restrict__ size_,
                             const float* __restrict__ heading) {
    int m = blockIdx.x * blockDim.x + threadIdx.x;
    if (m >= M1) return;
    int g  = m & 63;
    int bk = m >> 6;
    float sx = size_[bk * 3 + 0], sy = size_[bk * 3 + 1], sz = size_[bk * 3 + 2];
    float h  = heading[bk];
    float ch = cosf(h), sh = sinf(h);
    float gx = -1.f + (float)( g >> 4      ) * (2.f / 3.f);
    float gy = -1.f + (float)((g >> 2) & 3 ) * (2.f / 3.f);
    float gz = -1.f + (float)( g       & 3 ) * (2.f / 3.f);
    float ax = gx * sx, ay = gy * sy, az = gz * sz;
    float rx = ax * ch - ay * sh;
    float ry = ax * sh + ay * ch;
    float rz = az;
    float* row = g_X0 + (long long)m * LDA0;
    row[256] = rx; row[257] = ry; row[258] = rz;
    // zero the pad so the GEMM loader can read unconditionally (PERM zero-fill backup)
    #pragma unroll
    for (int p = 259; p < LDA0; ++p) row[p] = 0.f;
    g_wq[m * 3 + 0] = rx + center[bk * 3 + 0];
    g_wq[m * 3 + 1] = ry + center[bk * 3 + 1];
    g_wq[m * 3 + 2] = rz + center[bk * 3 + 2];
}

// 3-NN per query over 1024 seeds (seeds cached in SMEM), inverse-distance weights
__global__ void k_threenn(const float* __restrict__ seed_xyz) {
    __shared__ float4 sp[NS];
    int b = blockIdx.x >> 7;
    int q = ((blockIdx.x & 127) << 7) + threadIdx.x;
    for (int i = threadIdx.x; i < NS; i += blockDim.x) {
        float x = seed_xyz[((long long)b * NS + i) * 3 + 0];
        float y = seed_xyz[((long long)b * NS + i) * 3 + 1];
        float z = seed_xyz[((long long)b * NS + i) * 3 + 2];
        sp[i] = make_float4(x, y, z, x * x + y * y + z * z);
    }
    __syncthreads();
    int m = b * QQ + q;
    float qx = g_wq[m * 3 + 0], qy = g_wq[m * 3 + 1], qz = g_wq[m * 3 + 2];
    float qq = qx * qx + qy * qy + qz * qz;
    float d0 = 1e30f, d1 = 1e30f, d2 = 1e30f;
    int   i0 = 0, i1 = 0, i2 = 0;
    for (int n = 0; n < NS; ++n) {
        float4 p = sp[n];
        float d = qq + p.w - 2.f * (qx * p.x + qy * p.y + qz * p.z);
        if (d < d2) {
            if (d < d1) {
                d2 = d1; i2 = i1;
                if (d < d0) { d1 = d0; i1 = i0; d0 = d; i0 = n; }
                else        { d1 = d;  i1 = n; }
            } else { d2 = d; i2 = n; }
        }
    }
    int ii[3] = {i0, i1, i2};
    float w[3];
#pragma unroll
    for (int j = 0; j < 3; ++j) {
        float4 p = sp[ii[j]];
        float dx = p.x - qx, dy = p.y - qy, dz = p.z - qz;
        float dist = sqrtf(dx * dx + dy * dy + dz * dz);
        w[j] = 1.f / (dist + 1e-8f);
    }
    float inv = 1.f / (w[0] + w[1] + w[2]);
#pragma unroll
    for (int j = 0; j < 3; ++j) {
        g_idx3[m * 3 + j] = ii[j];
        g_w3[m * 3 + j]   = w[j] * inv;
    }
}

// weighted feature gather: one warp per query, float4 rows of g_featT -> X0[:,0:256)
__global__ void k_interp() {
    int warp = (blockIdx.x * blockDim.x + threadIdx.x) >> 5;
    int lane = threadIdx.x & 31;
    int m = warp;
    int b = m >> 14;
    int i0 = g_idx3[m * 3 + 0], i1 = g_idx3[m * 3 + 1], i2 = g_idx3[m * 3 + 2];
    float w0 = g_w3[m * 3 + 0], w1 = g_w3[m * 3 + 1], w2 = g_w3[m * 3 + 2];
    const float4* f0 = (const float4*)(g_featT + ((long long)b * NS + i0) * CF);
    const float4* f1 = (const float4*)(g_featT + ((long long)b * NS + i1) * CF);
    const float4* f2 = (const float4*)(g_featT + ((long long)b * NS + i2) * CF);
    float4* dst = (float4*)(g_X0 + (long long)m * LDA0);
#pragma unroll
    for (int c = lane; c < CF / 4; c += 32) {
        float4 a = f0[c], bq = f1[c], cq = f2[c];
        dst[c] = make_float4(w0 * a.x + w1 * bq.x + w2 * cq.x,
                             w0 * a.y + w1 * bq.y + w2 * cq.y,
                             w0 * a.z + w1 * bq.z + w2 * cq.z,
                             w0 * a.w + w1 * bq.w + w2 * cq.w);
    }
}

// -------- split-bf16 tensor-core GEMM: C[m,n] = sum_k act(A[m,k]) * W[n,k] + bias[n] --------
// 128x128 tile, K-chunks of 32, m16n8k16 bf16 MMA, acc += aL*bH + aH*bL + aH*bH.
// 8 warps (2 over M x 4 over N), warp tile 64x32. 2 CTAs/SM.
// act = identity, or fused BN(scale/shift)+ReLU of previous layer when BNA.
// PERM: layer-0 column permutation of W (X0 stored interp-first); zero-fill k >= KDIM.
template <int KDIM, bool BNA, bool PERM>
__global__ void __launch_bounds__(256, 2)
k_gemm_bf(const float* __restrict__ A, int lda,
          const float* __restrict__ W,
          const float* __restrict__ bias,
          const float* __restrict__ scl,
          const float* __restrict__ shf,
          float* __restrict__ C) {
    // kp = k/2 pair index; word = {k_even, k_odd} packed bf16
    __shared__ uint32_t AsH[16][136];
    __shared__ uint32_t AsL[16][136];
    __shared__ uint32_t WsH[16][136];
    __shared__ uint32_t WsL[16][136];
    const int tid  = threadIdx.x;
    const int lane = tid & 31;
    const int warp = tid >> 5;
    const int g    = lane >> 2;        // 0..7
    const int q    = lane & 3;         // 0..3
    const int wm   = warp & 1;         // 2 warps over M
    const int wn   = warp >> 1;        // 4 warps over N
    const int bm   = blockIdx.x * 128;

    float acc[4][4][4];
#pragma unroll
    for (int i = 0; i < 4; ++i)
#pragma unroll
        for (int j = 0; j < 4; ++j)
#pragma unroll
            for (int r = 0; r < 4; ++r) acc[i][j][r] = 0.f;

    const int ldrow = tid >> 1;         // 0..127 (row of A / row n of W)
    const int ldkv  = (tid & 1) * 16;   // k offset within chunk: 0 or 16
    const int KPHYS = PERM ? LDA0 : KDIM;
    const int NCH   = KPHYS / 32;       // 9 for layer0, 4 for K=128

    for (int ch = 0; ch < NCH; ++ch) {
        const int k0 = ch * 32;
        // ---- A tile: 16 fp32 per thread -> split -> AsH/AsL[kp][m] ----
        {
            const float* ap = A + (long long)(bm + ldrow) * lda + k0 + ldkv;
            float4 u0 = *(const float4*)(ap + 0);
            float4 u1 = *(const float4*)(ap + 4);
            float4 u2 = *(const float4*)(ap + 8);
            float4 u3 = *(const float4*)(ap + 12);
            float v[16] = {u0.x,u0.y,u0.z,u0.w, u1.x,u1.y,u1.z,u1.w,
                           u2.x,u2.y,u2.z,u2.w, u3.x,u3.y,u3.z,u3.w};
            // PERM: pad cols (>=259) were pre-zeroed in g_X0, loads safe as-is
            if (BNA) {
#pragma unroll
                for (int i = 0; i < 16; ++i) {
                    int k = k0 + ldkv + i;   // BNA only with KDIM=128: always valid
                    v[i] = fmaxf(v[i] * scl[k] + shf[k], 0.f);
                }
            }
            const int kp0 = (k0 ? 0 : 0) + ldkv / 2;  // pair index within chunk: 0 or 8
#pragma unroll
            for (int i = 0; i < 8; ++i) {
                uint32_t hi, lo;
                split2_bf16(v[2 * i], v[2 * i + 1], hi, lo);
                AsH[kp0 + i][ldrow] = hi;
                AsL[kp0 + i][ldrow] = lo;
            }
        }
        // ---- W tile -> WsH/WsL[kp][n] ----
        {
            const int n = ldrow;
            float v[16];
            if (PERM) {
#pragma unroll
                for (int i = 0; i < 16; ++i) {
                    int k = k0 + ldkv + i;
                    v[i] = 0.f;
                    if (k < KDIM) {
                        int kl = (k < 256) ? (k + 3) : (k - 256);
                        v[i] = W[n * KDIM + kl];
                    }
                }
            } else {
                const float* wp = W + (long long)n * KDIM + k0 + ldkv;
                float4 u0 = *(const float4*)(wp + 0);
                float4 u1 = *(const float4*)(wp + 4);
                float4 u2 = *(const float4*)(wp + 8);
                float4 u3 = *(const float4*)(wp + 12);
                v[0]=u0.x; v[1]=u0.y; v[2]=u0.z; v[3]=u0.w;
                v[4]=u1.x; v[5]=u1.y; v[6]=u1.z; v[7]=u1.w;
                v[8]=u2.x; v[9]=u2.y; v[10]=u2.z; v[11]=u2.w;
                v[12]=u3.x; v[13]=u3.y; v[14]=u3.z; v[15]=u3.w;
            }
            const int kp0 = ldkv / 2;
#pragma unroll
            for (int i = 0; i < 8; ++i) {
                uint32_t hi, lo;
                split2_bf16(v[2 * i], v[2 * i + 1], hi, lo);
                WsH[kp0 + i][n] = hi;
                WsL[kp0 + i][n] = lo;
            }
        }
        __syncthreads();

        // two k16 steps per chunk (kp windows [0,8) and [8,16))
#pragma unroll
        for (int kb = 0; kb < 16; kb += 8) {
            uint32_t bH[4][2], bL[4][2];
#pragma unroll
            for (int nt = 0; nt < 4; ++nt) {
                int nbase = wn * 32 + nt * 8;
                bH[nt][0] = WsH[kb + q    ][nbase + g];
                bH[nt][1] = WsH[kb + q + 4][nbase + g];
                bL[nt][0] = WsL[kb + q    ][nbase + g];
                bL[nt][1] = WsL[kb + q + 4][nbase + g];
            }
#pragma unroll
            for (int mt = 0; mt < 4; ++mt) {
                int mbase = wm * 64 + mt * 16;
                uint32_t aH0 = AsH[kb + q    ][mbase + g    ];
                uint32_t aH1 = AsH[kb + q    ][mbase + g + 8];
                uint32_t aH2 = AsH[kb + q + 4][mbase + g    ];
                uint32_t aH3 = AsH[kb + q + 4][mbase + g + 8];
                uint32_t aL0 = AsL[kb + q    ][mbase + g    ];
                uint32_t aL1 = AsL[kb + q    ][mbase + g + 8];
                uint32_t aL2 = AsL[kb + q + 4][mbase + g    ];
                uint32_t aL3 = AsL[kb + q + 4][mbase + g + 8];
#pragma unroll
                for (int nt = 0; nt < 4; ++nt) {
                    mma_bf16(acc[mt][nt][0], acc[mt][nt][1], acc[mt][nt][2], acc[mt][nt][3],
                             aL0, aL1, aL2, aL3, bH[nt][0], bH[nt][1]);
                    mma_bf16(acc[mt][nt][0], acc[mt][nt][1], acc[mt][nt][2], acc[mt][nt][3],
                             aH0, aH1, aH2, aH3, bL[nt][0], bL[nt][1]);
                    mma_bf16(acc[mt][nt][0], acc[mt][nt][1], acc[mt][nt][2], acc[mt][nt][3],
                             aH0, aH1, aH2, aH3, bH[nt][0], bH[nt][1]);
                }
            }
        }
        __syncthreads();
    }

    // ---- epilogue: bias + store ----
#pragma unroll
    for (int nt = 0; nt < 4; ++nt) {
        int col = wn * 32 + nt * 8 + q * 2;
        float bx = bias[col], by = bias[col + 1];
#pragma unroll
        for (int mt = 0; mt < 4; ++mt) {
            int r0 = bm + wm * 64 + mt * 16 + g;
            float2 o0 = make_float2(acc[mt][nt][0] + bx, acc[mt][nt][1] + by);
            float2 o1 = make_float2(acc[mt][nt][2] + bx, acc[mt][nt][3] + by);
            *(float2*)(C + (long long)r0 * 128 + col)       = o0;
            *(float2*)(C + (long long)(r0 + 8) * 128 + col) = o1;
        }
    }
}

// -------- fp32 SIMT GEMM kept for the tiny FC layers (M=1024) --------
template <int KDIM, bool BNA>
__global__ void __launch_bounds__(256)
k_gemm(const float* __restrict__ A, int lda,
       const float* __restrict__ W,
       const float* __restrict__ bias,
       const float* __restrict__ scl,
       const float* __restrict__ shf,
       float* __restrict__ C) {
    __shared__ float As[16][128];
    __shared__ float Ws2[16][128];
    int tid = threadIdx.x;
    int bm  = blockIdx.x * 128;
    int tx  = tid & 15, ty = tid >> 4;
    float acc[8][8];
#pragma unroll
    for (int i = 0; i < 8; ++i)
#pragma unroll
        for (int j = 0; j < 8; ++j) acc[i][j] = 0.f;

    const int KT = (KDIM + 15) / 16;
    for (int kt = 0; kt < KT; ++kt) {
        int k0 = kt * 16;
#pragma unroll
        for (int r = 0; r < 2; ++r) {
            int row = (tid >> 2) + r * 64;
            int kv  = (tid & 3) * 4;
            int k   = k0 + kv;
            float4 v = *reinterpret_cast<const float4*>(A + (long long)(bm + row) * lda + k);
            if (BNA) {
                v.x = fmaxf(v.x * scl[k + 0] + shf[k + 0], 0.f);
                v.y = fmaxf(v.y * scl[k + 1] + shf[k + 1], 0.f);
                v.z = fmaxf(v.z * scl[k + 2] + shf[k + 2], 0.f);
                v.w = fmaxf(v.w * scl[k + 3] + shf[k + 3], 0.f);
            }
            As[kv + 0][row] = v.x;
            As[kv + 1][row] = v.y;
            As[kv + 2][row] = v.z;
            As[kv + 3][row] = v.w;
        }
        {
            int n  = tid >> 1;
            int kb = (tid & 1) * 8;
#pragma unroll
            for (int i = 0; i < 8; ++i) {
                int k = k0 + kb + i;
                Ws2[kb + i][n] = W[n * KDIM + k];
            }
        }
        __syncthreads();
#pragma unroll
        for (int kk = 0; kk < 16; ++kk) {
            float a[8], w8[8];
            *reinterpret_cast<float4*>(&a[0])  = *reinterpret_cast<const float4*>(&As[kk][ty * 8]);
            *reinterpret_cast<float4*>(&a[4])  = *reinterpret_cast<const float4*>(&As[kk][ty * 8 + 4]);
            *reinterpret_cast<float4*>(&w8[0]) = *reinterpret_cast<const float4*>(&Ws2[kk][tx * 8]);
            *reinterpret_cast<float4*>(&w8[4]) = *reinterpret_cast<const float4*>(&Ws2[kk][tx * 8 + 4]);
#pragma unroll
            for (int i = 0; i < 8; ++i)
#pragma unroll
                for (int j = 0; j < 8; ++j) acc[i][j] += a[i] * w8[j];
        }
        __syncthreads();
    }
    float bv[8];
#pragma unroll
    for (int j = 0; j < 8; ++j) bv[j] = bias[tx * 8 + j];
#pragma unroll
    for (int i = 0; i < 8; ++i) {
        long long off = (long long)(bm + ty * 8 + i) * 128 + tx * 8;
        float4 o0 = make_float4(acc[i][0] + bv[0], acc[i][1] + bv[1],
                                acc[i][2] + bv[2], acc[i][3] + bv[3]);
        float4 o1 = make_float4(acc[i][4] + bv[4], acc[i][5] + bv[5],
                                acc[i][6] + bv[6], acc[i][7] + bv[7]);
        *reinterpret_cast<float4*>(C + off)     = o0;
        *reinterpret_cast<float4*>(C + off + 4) = o1;
    }
}

// deterministic two-stage BN stats: per-block partial sums -> g_part
__global__ void k_stats(const float* __restrict__ Y, int M) {
    __shared__ float ss[256], sq[256];
    int c    = threadIdx.x & 127;
    int half = threadIdx.x >> 7;
    int rowsPer = M / gridDim.x;
    int r0 = blockIdx.x * rowsPer;
    float s = 0.f, s2 = 0.f;
    for (int r = r0 + half; r < r0 + rowsPer; r += 2) {
        float v = Y[(long long)r * 128 + c];
        s += v; s2 += v * v;
    }
    ss[threadIdx.x] = s; sq[threadIdx.x] = s2;
    __syncthreads();
    if (threadIdx.x < 128) {
        g_part[blockIdx.x * 256 + threadIdx.x]       = ss[threadIdx.x] + ss[threadIdx.x + 128];
        g_part[blockIdx.x * 256 + 128 + threadIdx.x] = sq[threadIdx.x] + sq[threadIdx.x + 128];
    }
}

__global__ void k_bnfin(int NB, float Minv,
                        const float* __restrict__ gamma,
                        const float* __restrict__ beta,
                        int slot) {
    int c = threadIdx.x;
    float s = 0.f, s2 = 0.f;
    for (int b = 0; b < NB; ++b) {
        s  += g_part[b * 256 + c];
        s2 += g_part[b * 256 + 128 + c];
    }
    float mean = s * Minv;
    float var  = s2 * Minv - mean * mean;
    float rstd = rsqrtf(var + 1e-5f);
    float sc   = gamma[c] * rstd;
    g_scale[slot * 128 + c] = sc;
    g_shift[slot * 128 + c] = beta[c] - mean * sc;
}

// BN3 + ReLU + maxpool over the 64 grid points -> g_F [1024, 128]
__global__ void k_maxpool() {
    int bk = blockIdx.x;
    int c  = threadIdx.x;
    float sc = g_scale[2 * 128 + c], sf = g_shift[2 * 128 + c];
    const float* base = g_Y3 + (long long)bk * 64 * 128 + c;
    float mx = -1e30f;
#pragma unroll 4
    for (int g = 0; g < 64; ++g) {
        float v = base[g * 128] * sc + sf;
        mx = fmaxf(mx, v);
    }
    g_F[bk * 128 + c] = fmaxf(mx, 0.f);
}

// BN5+ReLU on N2, project to the last 18 of 77 output channels
__global__ void k_final(const float* __restrict__ cw3,
                        const float* __restrict__ cb3,
                        float* __restrict__ out) {
    int t = blockIdx.x * blockDim.x + threadIdx.x;
    if (t >= MFC * IOUS) return;
    int j   = t % IOUS;
    int row = t / IOUS;
    int o   = (OUTC - IOUS) + j;
    const float* wrow = cw3 + o * 128;
    const float* x    = g_N2 + row * 128;
    float acc = cb3[o];
#pragma unroll 8
    for (int i = 0; i < 128; ++i) {
        float v = fmaxf(x[i] * g_scale[4 * 128 + i] + g_shift[4 * 128 + i], 0.f);
        acc += v * wrow[i];
    }
    out[t] = acc;
}

// ---------------- launcher ----------------
extern "C" void kernel_launch(void* const* d_in, const int* in_sizes, int n_in,
                              void* d_out, int out_size) {
    const float* center  = (const float*)d_in[0];
    const float* size_   = (const float*)d_in[1];
    const float* heading = (const float*)d_in[2];
    const float* sxyz    = (const float*)d_in[3];
    const float* sfeat   = (const float*)d_in[4];
    const float* w0  = (const float*)d_in[5];
    const float* b0  = (const float*)d_in[6];
    const float* g0  = (const float*)d_in[7];
    const float* be0 = (const float*)d_in[8];
    const float* w1  = (const float*)d_in[9];
    const float* b1  = (const float*)d_in[10];
    const float* g1  = (const float*)d_in[11];
    const float* be1 = (const float*)d_in[12];
    const float* w2  = (const float*)d_in[13];
    const float* b2  = (const float*)d_in[14];
    const float* g2  = (const float*)d_in[15];
    const float* be2 = (const float*)d_in[16];
    const float* cw1 = (const float*)d_in[17];
    const float* cb1 = (const float*)d_in[18];
    const float* g3  = (const float*)d_in[19];
    const float* be3 = (const float*)d_in[20];
    const float* cw2 = (const float*)d_in[21];
    const float* cb2 = (const float*)d_in[22];
    const float* g4  = (const float*)d_in[23];
    const float* be4 = (const float*)d_in[24];
    const float* cw3 = (const float*)d_in[25];
    const float* cb3 = (const float*)d_in[26];
    float* out = (float*)d_out;

    void *pX0, *pY1, *pY2, *pY3, *pF, *pN1, *pN2, *pSC, *pSH;
    cudaGetSymbolAddress(&pX0, g_X0);
    cudaGetSymbolAddress(&pY1, g_Y1);
    cudaGetSymbolAddress(&pY2, g_Y2);
    cudaGetSymbolAddress(&pY3, g_Y3);
    cudaGetSymbolAddress(&pF,  g_F);
    cudaGetSymbolAddress(&pN1, g_N1);
    cudaGetSymbolAddress(&pN2, g_N2);
    cudaGetSymbolAddress(&pSC, g_scale);
    cudaGetSymbolAddress(&pSH, g_shift);
    float* X0 = (float*)pX0;
    float* Y1 = (float*)pY1;
    float* Y2 = (float*)pY2;
    float* Y3 = (float*)pY3;
    float* F  = (float*)pF;
    float* N1 = (float*)pN1;
    float* N2 = (float*)pN2;
    float* SC = (float*)pSC;
    float* SH = (float*)pSH;

    // stage 1: geometry + interpolation inputs
    k_transpose<<<dim3(NS / 32, CF / 32, BB), dim3(32, 8)>>>(sfeat);
    k_gridpoints<<<M1 / 256, 256>>>(center, size_, heading);
    k_threenn<<<BB * 128, 128>>>(sxyz);
    k_interp<<<M1 / 8, 256>>>();

    // stage 2: SharedMLP on tensor cores (split-bf16), training BN folded into next layer's load
    k_gemm_bf<CIN0, false, true><<<M1 / 128, 256>>>(X0, LDA0, w0, b0, nullptr, nullptr, Y1);
    k_stats<<<128, 256>>>(Y1, M1);
    k_bnfin<<<1, 128>>>(128, 1.f / M1, g0, be0, 0);

    k_gemm_bf<HH, true, false><<<M1 / 128, 256>>>(Y1, HH, w1, b1, SC + 0 * 128, SH + 0 * 128, Y2);
    k_stats<<<128, 256>>>(Y2, M1);
    k_bnfin<<<1, 128>>>(128, 1.f / M1, g1, be1, 1);

    k_gemm_bf<HH, true, false><<<M1 / 128, 256>>>(Y2, HH, w2, b2, SC + 1 * 128, SH + 1 * 128, Y3);
    k_stats<<<128, 256>>>(Y3, M1);
    k_bnfin<<<1, 128>>>(128, 1.f / M1, g2, be2, 2);

    // stage 3: pool + FC head (fp32, tiny)
    k_maxpool<<<MFC, 128>>>();

    k_gemm<HH, false><<<MFC / 128, 256>>>(F, HH, cw1, cb1, nullptr, nullptr, N1);
    k_stats<<<8, 256>>>(N1, MFC);
    k_bnfin<<<1, 128>>>(8, 1.f / MFC, g3, be3, 3);

    k_gemm<HH, true><<<MFC / 128, 256>>>(N1, HH, cw2, cb2, SC + 3 * 128, SH + 3 * 128, N2);
    k_stats<<<8, 256>>>(N2, MFC);
    k_bnfin<<<1, 128>>>(8, 1.f / MFC, g4, be4, 4);

    k_final<<<(MFC * IOUS + 255) / 256, 256>>>(cw3, cb3, out);
}

// round 6
// speedup vs baseline: 1.9653x; 1.5223x over previous
#include <cuda_runtime.h>
#include <cuda_bf16.h>
#include <math.h>
#include <stdint.h>

// ---------------- problem constants ----------------
static constexpr int BB   = 4;
static constexpr int KK   = 256;
static constexpr int NS   = 1024;      // seeds
static constexpr int CF   = 256;       // seed feature channels
static constexpr int GPP  = 64;        // grid points per proposal
static constexpr int QQ   = KK * GPP;  // 16384 queries per batch
static constexpr int M1   = BB * QQ;   // 65536 rows for conv layers
static constexpr int CIN0 = CF + 3;    // 259 logical input channels
static constexpr int LDA0 = 288;       // padded phys leading dim for X0 (9 k-chunks of 32)
static constexpr int HH   = 128;
static constexpr int MFC  = BB * KK;   // 1024 rows for FC layers
static constexpr int IOUS = 18;
static constexpr int OUTC = 77;

// X0 physical layout: cols [0,256) = interp features, [256,259) = rel xyz, [259,288) pad=0.
// Layer-0 W load permutes: phys k<256 -> logical k+3 ; phys 256..258 -> logical k-256.

// ---------------- scratch (static device memory; no allocations) ----------------
__device__ float g_X0[(long long)M1 * LDA0];
__device__ float g_wq[M1 * 3];
__device__ float g_featT[BB * NS * CF];        // [b][n][c]
__device__ int   g_idx3[M1 * 3];
__device__ float g_w3[M1 * 3];
__device__ float g_Y1[(long long)M1 * HH];
__device__ float g_Y2[(long long)M1 * HH];
__device__ float g_F [MFC * HH];               // RAW maxpool output (pre-BN3)
__device__ float g_N1[MFC * HH];
__device__ float g_N2[MFC * HH];
__device__ float g_part[512 * 256];            // per-CTA partial BN stats
__device__ float g_scale[5 * 128];
__device__ float g_shift[5 * 128];

// ---------------- small helpers ----------------
// split two fp32 values into packed-bf16 (hi pair, lo pair); word = {k_even, k_odd}
__device__ __forceinline__ void split2_bf16(float v0, float v1, uint32_t& hi, uint32_t& lo) {
    __nv_bfloat16 h0 = __float2bfloat16_rn(v0);
    __nv_bfloat16 h1 = __float2bfloat16_rn(v1);
    float l0 = v0 - __bfloat162float(h0);
    float l1 = v1 - __bfloat162float(h1);
    __nv_bfloat162 hp = __halves2bfloat162(h0, h1);
    __nv_bfloat162 lp = __floats2bfloat162_rn(l0, l1);
    hi = *reinterpret_cast<uint32_t*>(&hp);
    lo = *reinterpret_cast<uint32_t*>(&lp);
}

__device__ __forceinline__ void mma_bf16(float& c0, float& c1, float& c2, float& c3,
                                         uint32_t a0, uint32_t a1, uint32_t a2, uint32_t a3,
                                         uint32_t b0, uint32_t b1) {
    asm volatile(
        "mma.sync.aligned.m16n8k16.row.col.f32.bf16.bf16.f32 "
        "{%0,%1,%2,%3}, {%4,%5,%6,%7}, {%8,%9}, {%0,%1,%2,%3};"
        : "+f"(c0), "+f"(c1), "+f"(c2), "+f"(c3)
        : "r"(a0), "r"(a1), "r"(a2), "r"(a3), "r"(b0), "r"(b1));
}

// ---------------- kernels ----------------

// seed_features [b][c][n] -> g_featT [b][n][c]
__global__ void k_transpose(const float* __restrict__ feat) {
    __shared__ float tile[32][33];
    int b  = blockIdx.z;
    int n0 = blockIdx.x * 32;
    int c0 = blockIdx.y * 32;
    const float* src = feat    + (long long)b * CF * NS;
    float*       dst = g_featT + (long long)b * NS * CF;
#pragma unroll
    for (int r = 0; r < 4; ++r) {
        int c = c0 + threadIdx.y + r * 8;
        tile[threadIdx.y + r * 8][threadIdx.x] = src[c * NS + n0 + threadIdx.x];
    }
    __syncthreads();
#pragma unroll
    for (int r = 0; r < 4; ++r) {
        int n = n0 + threadIdx.y + r * 8;
        dst[n * CF + c0 + threadIdx.x] = tile[threadIdx.x][threadIdx.y + r * 8];
    }
}

// rotate+scale grid, write rel into X0[:, 256:259] (+zero pad) and world points -> g_wq
__global__ void k_gridpoints(const float* __restrict__ center,
                             const float* __restrict__ size_,
                             const float* __restrict__ heading) {
    int m = blockIdx.x * blockDim.x + threadIdx.x;
    if (m >= M1) return;
    int g  = m & 63;
    int bk = m >> 6;
    float sx = size_[bk * 3 + 0], sy = size_[bk * 3 + 1], sz = size_[bk * 3 + 2];
    float h  = heading[bk];
    float ch = cosf(h), sh = sinf(h);
    float gx = -1.f + (float)( g >> 4      ) * (2.f / 3.f);
    float gy = -1.f + (float)((g >> 2) & 3 ) * (2.f / 3.f);
    float gz = -1.f + (float)( g       & 3 ) * (2.f / 3.f);
    float ax = gx * sx, ay = gy * sy, az = gz * sz;
    float rx = ax * ch - ay * sh;
    float ry = ax * sh + ay * ch;
    float rz = az;
    float* row = g_X0 + (long long)m * LDA0;
    row[256] = rx; row[257] = ry; row[258] = rz;
#pragma unroll
    for (int p = 259; p < LDA0; ++p) row[p] = 0.f;
    g_wq[m * 3 + 0] = rx + center[bk * 3 + 0];
    g_wq[m * 3 + 1] = ry + center[bk * 3 + 1];
    g_wq[m * 3 + 2] = rz + center[bk * 3 + 2];
}

// 3-NN per query over 1024 seeds (seeds cached in SMEM), inverse-distance weights
__global__ void k_threenn(const float* __restrict__ seed_xyz) {
    __shared__ float4 sp[NS];
    int b = blockIdx.x >> 7;
    int q = ((blockIdx.x & 127) << 7) + threadIdx.x;
    for (int i = threadIdx.x; i < NS; i += blockDim.x) {
        float x = seed_xyz[((long long)b * NS + i) * 3 + 0];
        float y = seed_xyz[((long long)b * NS + i) * 3 + 1];
        float z = seed_xyz[((long long)b * NS + i) * 3 + 2];
        sp[i] = make_float4(x, y, z, x * x + y * y + z * z);
    }
    __syncthreads();
    int m = b * QQ + q;
    float qx = g_wq[m * 3 + 0], qy = g_wq[m * 3 + 1], qz = g_wq[m * 3 + 2];
    float qq = qx * qx + qy * qy + qz * qz;
    float d0 = 1e30f, d1 = 1e30f, d2 = 1e30f;
    int   i0 = 0, i1 = 0, i2 = 0;
    for (int n = 0; n < NS; ++n) {
        float4 p = sp[n];
        float d = qq + p.w - 2.f * (qx * p.x + qy * p.y + qz * p.z);
        if (d < d2) {
            if (d < d1) {
                d2 = d1; i2 = i1;
                if (d < d0) { d1 = d0; i1 = i0; d0 = d; i0 = n; }
                else        { d1 = d;  i1 = n; }
            } else { d2 = d; i2 = n; }
        }
    }
    int ii[3] = {i0, i1, i2};
    float w[3];
#pragma unroll
    for (int j = 0; j < 3; ++j) {
        float4 p = sp[ii[j]];
        float dx = p.x - qx, dy = p.y - qy, dz = p.z - qz;
        float dist = sqrtf(dx * dx + dy * dy + dz * dz);
        w[j] = 1.f / (dist + 1e-8f);
    }
    float inv = 1.f / (w[0] + w[1] + w[2]);
#pragma unroll
    for (int j = 0; j < 3; ++j) {
        g_idx3[m * 3 + j] = ii[j];
        g_w3[m * 3 + j]   = w[j] * inv;
    }
}

// weighted feature gather: one warp per query, float4 rows of g_featT -> X0[:,0:256)
__global__ void k_interp() {
    int warp = (blockIdx.x * blockDim.x + threadIdx.x) >> 5;
    int lane = threadIdx.x & 31;
    int m = warp;
    int b = m >> 14;
    int i0 = g_idx3[m * 3 + 0], i1 = g_idx3[m * 3 + 1], i2 = g_idx3[m * 3 + 2];
    float w0 = g_w3[m * 3 + 0], w1 = g_w3[m * 3 + 1], w2 = g_w3[m * 3 + 2];
    const float4* f0 = (const float4*)(g_featT + ((long long)b * NS + i0) * CF);
    const float4* f1 = (const float4*)(g_featT + ((long long)b * NS + i1) * CF);
    const float4* f2 = (const float4*)(g_featT + ((long long)b * NS + i2) * CF);
    float4* dst = (float4*)(g_X0 + (long long)m * LDA0);
#pragma unroll
    for (int c = lane; c < CF / 4; c += 32) {
        float4 a = f0[c], bq = f1[c], cq = f2[c];
        dst[c] = make_float4(w0 * a.x + w1 * bq.x + w2 * cq.x,
                             w0 * a.y + w1 * bq.y + w2 * cq.y,
                             w0 * a.z + w1 * bq.z + w2 * cq.z,
                             w0 * a.w + w1 * bq.w + w2 * cq.w);
    }
}

// ---- split-bf16 tensor-core GEMM with fused epilogue ----
// C[m,n] = sum_k act(A[m,k]) * W[n,k] + bias[n]
// 128x128 tile, K-chunks of 32, m16n8k16 bf16 MMA, acc += aL*bH + aH*bL + aH*bH.
// 8 warps (2 over M x 4 over N). A-chunk register-prefetched one iteration ahead.
// Epilogue always emits per-CTA partial BN stats (sum, sumsq per channel) to g_part.
// POOL: also emit per-64-row-group raw channel max to poolOut (2 proposals per CTA).
// STOREC: write C tile to GMEM.
template <int KDIM, bool BNA, bool PERM, bool POOL, bool STOREC>
__global__ void __launch_bounds__(256, 2)
k_gemm_bf(const float* __restrict__ A, int lda,
          const float* __restrict__ W,
          const float* __restrict__ bias,
          const float* __restrict__ scl,
          const float* __restrict__ shf,
          float* __restrict__ C,
          float* __restrict__ partOut,
          float* __restrict__ poolOut) {
    __shared__ uint32_t AsH[16][136];
    __shared__ uint32_t AsL[16][136];
    __shared__ uint32_t WsH[16][136];
    __shared__ uint32_t WsL[16][136];
    __shared__ float redS[2][128];
    __shared__ float redQ[2][128];
    __shared__ float redM[2][128];

    const int tid  = threadIdx.x;
    const int lane = tid & 31;
    const int warp = tid >> 5;
    const int g    = lane >> 2;        // 0..7
    const int q    = lane & 3;         // 0..3
    const int wm   = warp & 1;         // 2 warps over M
    const int wn   = warp >> 1;        // 4 warps over N
    const int bm   = blockIdx.x * 128;

    float acc[4][4][4];
#pragma unroll
    for (int i = 0; i < 4; ++i)
#pragma unroll
        for (int j = 0; j < 4; ++j)
#pragma unroll
            for (int r = 0; r < 4; ++r) acc[i][j][r] = 0.f;

    const int ldrow = tid >> 1;         // 0..127
    const int ldkv  = (tid & 1) * 16;   // 0 or 16
    const int KPHYS = PERM ? LDA0 : KDIM;
    const int NCH   = KPHYS / 32;       // 9 for layer0, 4 for K=128

    float vA[16];
    // prefetch chunk 0
    {
        const float* ap = A + (long long)(bm + ldrow) * lda + ldkv;
        float4 u0 = *(const float4*)(ap + 0);
        float4 u1 = *(const float4*)(ap + 4);
        float4 u2 = *(const float4*)(ap + 8);
        float4 u3 = *(const float4*)(ap + 12);
        vA[0]=u0.x; vA[1]=u0.y; vA[2]=u0.z; vA[3]=u0.w;
        vA[4]=u1.x; vA[5]=u1.y; vA[6]=u1.z; vA[7]=u1.w;
        vA[8]=u2.x; vA[9]=u2.y; vA[10]=u2.z; vA[11]=u2.w;
        vA[12]=u3.x; vA[13]=u3.y; vA[14]=u3.z; vA[15]=u3.w;
    }

    for (int ch = 0; ch < NCH; ++ch) {
        const int k0 = ch * 32;
        // ---- split staged A chunk -> SMEM ----
        {
            float v[16];
#pragma unroll
            for (int i = 0; i < 16; ++i) v[i] = vA[i];
            if (BNA) {
#pragma unroll
                for (int i = 0; i < 16; ++i) {
                    int k = k0 + ldkv + i;   // BNA only with KDIM=128: always valid
                    v[i] = fmaxf(v[i] * scl[k] + shf[k], 0.f);
                }
            }
            const int kp0 = ldkv / 2;
#pragma unroll
            for (int i = 0; i < 8; ++i) {
                uint32_t hi, lo;
                split2_bf16(v[2 * i], v[2 * i + 1], hi, lo);
                AsH[kp0 + i][ldrow] = hi;
                AsL[kp0 + i][ldrow] = lo;
            }
        }
        // ---- W tile (L2-hot) -> SMEM ----
        {
            const int n = ldrow;
            float v[16];
            if (PERM) {
#pragma unroll
                for (int i = 0; i < 16; ++i) {
                    int k = k0 + ldkv + i;
                    v[i] = 0.f;
                    if (k < KDIM) {
                        int kl = (k < 256) ? (k + 3) : (k - 256);
                        v[i] = W[n * KDIM + kl];
                    }
                }
            } else {
                const float* wp = W + (long long)n * KDIM + k0 + ldkv;
                float4 u0 = *(const float4*)(wp + 0);
                float4 u1 = *(const float4*)(wp + 4);
                float4 u2 = *(const float4*)(wp + 8);
                float4 u3 = *(const float4*)(wp + 12);
                v[0]=u0.x; v[1]=u0.y; v[2]=u0.z; v[3]=u0.w;
                v[4]=u1.x; v[5]=u1.y; v[6]=u1.z; v[7]=u1.w;
                v[8]=u2.x; v[9]=u2.y; v[10]=u2.z; v[11]=u2.w;
                v[12]=u3.x; v[13]=u3.y; v[14]=u3.z; v[15]=u3.w;
            }
            const int kp0 = ldkv / 2;
#pragma unroll
            for (int i = 0; i < 8; ++i) {
                uint32_t hi, lo;
                split2_bf16(v[2 * i], v[2 * i + 1], hi, lo);
                WsH[kp0 + i][n] = hi;
                WsL[kp0 + i][n] = lo;
            }
        }
        __syncthreads();

        // ---- prefetch next A chunk (latency hidden behind MMAs) ----
        if (ch + 1 < NCH) {
            const float* ap = A + (long long)(bm + ldrow) * lda + (k0 + 32) + ldkv;
            float4 u0 = *(const float4*)(ap + 0);
            float4 u1 = *(const float4*)(ap + 4);
            float4 u2 = *(const float4*)(ap + 8);
            float4 u3 = *(const float4*)(ap + 12);
            vA[0]=u0.x; vA[1]=u0.y; vA[2]=u0.z; vA[3]=u0.w;
            vA[4]=u1.x; vA[5]=u1.y; vA[6]=u1.z; vA[7]=u1.w;
            vA[8]=u2.x; vA[9]=u2.y; vA[10]=u2.z; vA[11]=u2.w;
            vA[12]=u3.x; vA[13]=u3.y; vA[14]=u3.z; vA[15]=u3.w;
        }

        // ---- two k16 steps per chunk ----
#pragma unroll
        for (int kb = 0; kb < 16; kb += 8) {
            uint32_t bH[4][2], bL[4][2];
#pragma unroll
            for (int nt = 0; nt < 4; ++nt) {
                int nbase = wn * 32 + nt * 8;
                bH[nt][0] = WsH[kb + q    ][nbase + g];
                bH[nt][1] = WsH[kb + q + 4][nbase + g];
                bL[nt][0] = WsL[kb + q    ][nbase + g];
                bL[nt][1] = WsL[kb + q + 4][nbase + g];
            }
#pragma unroll
            for (int mt = 0; mt < 4; ++mt) {
                int mbase = wm * 64 + mt * 16;
                uint32_t aH0 = AsH[kb + q    ][mbase + g    ];
                uint32_t aH1 = AsH[kb + q    ][mbase + g + 8];
                uint32_t aH2 = AsH[kb + q + 4][mbase + g    ];
                uint32_t aH3 = AsH[kb + q + 4][mbase + g + 8];
                uint32_t aL0 = AsL[kb + q    ][mbase + g    ];
                uint32_t aL1 = AsL[kb + q    ][mbase + g + 8];
                uint32_t aL2 = AsL[kb + q + 4][mbase + g    ];
                uint32_t aL3 = AsL[kb + q + 4][mbase + g + 8];
#pragma unroll
                for (int nt = 0; nt < 4; ++nt) {
                    mma_bf16(acc[mt][nt][0], acc[mt][nt][1], acc[mt][nt][2], acc[mt][nt][3],
                             aL0, aL1, aL2, aL3, bH[nt][0], bH[nt][1]);
                    mma_bf16(acc[mt][nt][0], acc[mt][nt][1], acc[mt][nt][2], acc[mt][nt][3],
                             aH0, aH1, aH2, aH3, bL[nt][0], bL[nt][1]);
                    mma_bf16(acc[mt][nt][0], acc[mt][nt][1], acc[mt][nt][2], acc[mt][nt][3],
                             aH0, aH1, aH2, aH3, bH[nt][0], bH[nt][1]);
                }
            }
        }
        __syncthreads();
    }

    // ---- fused epilogue: bias, optional store, BN stats partials, optional maxpool ----
    float bsv[4][2];
#pragma unroll
    for (int nt = 0; nt < 4; ++nt) {
        int col = wn * 32 + nt * 8 + q * 2;
        bsv[nt][0] = bias[col];
        bsv[nt][1] = bias[col + 1];
    }
    float s[4][2], s2[4][2], mx[4][2];
#pragma unroll
    for (int nt = 0; nt < 4; ++nt)
#pragma unroll
        for (int j = 0; j < 2; ++j) { s[nt][j] = 0.f; s2[nt][j] = 0.f; mx[nt][j] = -1e30f; }

#pragma unroll
    for (int mt = 0; mt < 4; ++mt) {
#pragma unroll
        for (int nt = 0; nt < 4; ++nt) {
            float v0 = acc[mt][nt][0] + bsv[nt][0];
            float v1 = acc[mt][nt][1] + bsv[nt][1];
            float v2 = acc[mt][nt][2] + bsv[nt][0];
            float v3 = acc[mt][nt][3] + bsv[nt][1];
            if (STOREC) {
                int col = wn * 32 + nt * 8 + q * 2;
                int r0  = bm + wm * 64 + mt * 16 + g;
                *(float2*)(C + (long long)r0 * 128 + col)       = make_float2(v0, v1);
                *(float2*)(C + (long long)(r0 + 8) * 128 + col) = make_float2(v2, v3);
            }
            s [nt][0] += v0 + v2;       s [nt][1] += v1 + v3;
            s2[nt][0] += v0 * v0 + v2 * v2;
            s2[nt][1] += v1 * v1 + v3 * v3;
            if (POOL) {
                mx[nt][0] = fmaxf(mx[nt][0], fmaxf(v0, v2));
                mx[nt][1] = fmaxf(mx[nt][1], fmaxf(v1, v3));
            }
        }
    }
    // reduce across the 8 g-lanes (lane = g*4+q; g bits are lane bits 2..4)
#pragma unroll
    for (int nt = 0; nt < 4; ++nt)
#pragma unroll
        for (int j = 0; j < 2; ++j) {
#pragma unroll
            for (int mask = 4; mask <= 16; mask <<= 1) {
                s [nt][j] += __shfl_xor_sync(0xffffffff, s [nt][j], mask);
                s2[nt][j] += __shfl_xor_sync(0xffffffff, s2[nt][j], mask);
                if (POOL)
                    mx[nt][j] = fmaxf(mx[nt][j], __shfl_xor_sync(0xffffffff, mx[nt][j], mask));
            }
        }
    if (g == 0) {
#pragma unroll
        for (int nt = 0; nt < 4; ++nt)
#pragma unroll
            for (int j = 0; j < 2; ++j) {
                int col = wn * 32 + nt * 8 + q * 2 + j;
                redS[wm][col] = s[nt][j];
                redQ[wm][col] = s2[nt][j];
                if (POOL) redM[wm][col] = mx[nt][j];
            }
    }
    __syncthreads();
    if (tid < 128) {
        partOut[blockIdx.x * 256 + tid]       = redS[0][tid] + redS[1][tid];
        partOut[blockIdx.x * 256 + 128 + tid] = redQ[0][tid] + redQ[1][tid];
    }
    if (POOL) {
        // proposal bk = blockIdx*2 + wm-group; raw max (BN3+ReLU applied later via FC1 BNA)
        poolOut[(blockIdx.x * 2 + (tid >> 7)) * 128 + (tid & 127)] = redM[tid >> 7][tid & 127];
    }
}

// reduce 512 per-CTA partials -> folded BN scale/shift (1 block, 512 threads)
__global__ void k_bnfin512(float Minv,
                           const float* __restrict__ gamma,
                           const float* __restrict__ beta,
                           int slot) {
    __shared__ float rs[4][128], rq[4][128];
    int c  = threadIdx.x & 127;
    int sl = threadIdx.x >> 7;
    float s = 0.f, q = 0.f;
    for (int b = sl * 128; b < sl * 128 + 128; ++b) {
        s += g_part[b * 256 + c];
        q += g_part[b * 256 + 128 + c];
    }
    rs[sl][c] = s; rq[sl][c] = q;
    __syncthreads();
    if (threadIdx.x < 128) {
        float S = rs[0][c] + rs[1][c] + rs[2][c] + rs[3][c];
        float Q = rq[0][c] + rq[1][c] + rq[2][c] + rq[3][c];
        float mean = S * Minv;
        float var  = Q * Minv - mean * mean;
        float rstd = rsqrtf(var + 1e-5f);
        float sc   = gamma[c] * rstd;
        g_scale[slot * 128 + c] = sc;
        g_shift[slot * 128 + c] = beta[c] - mean * sc;
    }
}

// -------- fp32 SIMT GEMM for the tiny FC layers (M=1024) --------
template <int KDIM, bool BNA>
__global__ void __launch_bounds__(256)
k_gemm(const float* __restrict__ A, int lda,
       const float* __restrict__ W,
       const float* __restrict__ bias,
       const float* __restrict__ scl,
       const float* __restrict__ shf,
       float* __restrict__ C) {
    __shared__ float As[16][128];
    __shared__ float Ws2[16][128];
    int tid = threadIdx.x;
    int bm  = blockIdx.x * 128;
    int tx  = tid & 15, ty = tid >> 4;
    float acc[8][8];
#pragma unroll
    for (int i = 0; i < 8; ++i)
#pragma unroll
        for (int j = 0; j < 8; ++j) acc[i][j] = 0.f;

    const int KT = (KDIM + 15) / 16;
    for (int kt = 0; kt < KT; ++kt) {
        int k0 = kt * 16;
#pragma unroll
        for (int r = 0; r < 2; ++r) {
            int row = (tid >> 2) + r * 64;
            int kv  = (tid & 3) * 4;
            int k   = k0 + kv;
            float4 v = *reinterpret_cast<const float4*>(A + (long long)(bm + row) * lda + k);
            if (BNA) {
                v.x = fmaxf(v.x * scl[k + 0] + shf[k + 0], 0.f);
                v.y = fmaxf(v.y * scl[k + 1] + shf[k + 1], 0.f);
                v.z = fmaxf(v.z * scl[k + 2] + shf[k + 2], 0.f);
                v.w = fmaxf(v.w * scl[k + 3] + shf[k + 3], 0.f);
            }
            As[kv + 0][row] = v.x;
            As[kv + 1][row] = v.y;
            As[kv + 2][row] = v.z;
            As[kv + 3][row] = v.w;
        }
        {
            int n  = tid >> 1;
            int kb = (tid & 1) * 8;
#pragma unroll
            for (int i = 0; i < 8; ++i) {
                int k = k0 + kb + i;
                Ws2[kb + i][n] = W[n * KDIM + k];
            }
        }
        __syncthreads();
#pragma unroll
        for (int kk = 0; kk < 16; ++kk) {
            float a[8], w8[8];
            *reinterpret_cast<float4*>(&a[0])  = *reinterpret_cast<const float4*>(&As[kk][ty * 8]);
            *reinterpret_cast<float4*>(&a[4])  = *reinterpret_cast<const float4*>(&As[kk][ty * 8 + 4]);
            *reinterpret_cast<float4*>(&w8[0]) = *reinterpret_cast<const float4*>(&Ws2[kk][tx * 8]);
            *reinterpret_cast<float4*>(&w8[4]) = *reinterpret_cast<const float4*>(&Ws2[kk][tx * 8 + 4]);
#pragma unroll
            for (int i = 0; i < 8; ++i)
#pragma unroll
                for (int j = 0; j < 8; ++j) acc[i][j] += a[i] * w8[j];
        }
        __syncthreads();
    }
    float bv[8];
#pragma unroll
    for (int j = 0; j < 8; ++j) bv[j] = bias[tx * 8 + j];
#pragma unroll
    for (int i = 0; i < 8; ++i) {
        long long off = (long long)(bm + ty * 8 + i) * 128 + tx * 8;
        float4 o0 = make_float4(acc[i][0] + bv[0], acc[i][1] + bv[1],
                                acc[i][2] + bv[2], acc[i][3] + bv[3]);
        float4 o1 = make_float4(acc[i][4] + bv[4], acc[i][5] + bv[5],
                                acc[i][6] + bv[6], acc[i][7] + bv[7]);
        *reinterpret_cast<float4*>(C + off)     = o0;
        *reinterpret_cast<float4*>(C + off + 4) = o1;
    }
}

// deterministic two-stage BN stats for FC layers (small)
__global__ void k_stats(const float* __restrict__ Y, int M) {
    __shared__ float ss[256], sq[256];
    int c    = threadIdx.x & 127;
    int half = threadIdx.x >> 7;
    int rowsPer = M / gridDim.x;
    int r0 = blockIdx.x * rowsPer;
    float s = 0.f, s2 = 0.f;
    for (int r = r0 + half; r < r0 + rowsPer; r += 2) {
        float v = Y[(long long)r * 128 + c];
        s += v; s2 += v * v;
    }
    ss[threadIdx.x] = s; sq[threadIdx.x] = s2;
    __syncthreads();
    if (threadIdx.x < 128) {
        g_part[blockIdx.x * 256 + threadIdx.x]       = ss[threadIdx.x] + ss[threadIdx.x + 128];
        g_part[blockIdx.x * 256 + 128 + threadIdx.x] = sq[threadIdx.x] + sq[threadIdx.x + 128];
    }
}

__global__ void k_bnfin(int NB, float Minv,
                        const float* __restrict__ gamma,
                        const float* __restrict__ beta,
                        int slot) {
    int c = threadIdx.x;
    float s = 0.f, s2 = 0.f;
    for (int b = 0; b < NB; ++b) {
        s  += g_part[b * 256 + c];
        s2 += g_part[b * 256 + 128 + c];
    }
    float mean = s * Minv;
    float var  = s2 * Minv - mean * mean;
    float rstd = rsqrtf(var + 1e-5f);
    float sc   = gamma[c] * rstd;
    g_scale[slot * 128 + c] = sc;
    g_shift[slot * 128 + c] = beta[c] - mean * sc;
}

// BN5+ReLU on N2, project to the last 18 of 77 output channels
__global__ void k_final(const float* __restrict__ cw3,
                        const float* __restrict__ cb3,
                        float* __restrict__ out) {
    int t = blockIdx.x * blockDim.x + threadIdx.x;
    if (t >= MFC * IOUS) return;
    int j   = t % IOUS;
    int row = t / IOUS;
    int o   = (OUTC - IOUS) + j;
    const float* wrow = cw3 + o * 128;
    const float* x    = g_N2 + row * 128;
    float acc = cb3[o];
#pragma unroll 8
    for (int i = 0; i < 128; ++i) {
        float v = fmaxf(x[i] * g_scale[4 * 128 + i] + g_shift[4 * 128 + i], 0.f);
        acc += v * wrow[i];
    }
    out[t] = acc;
}

// ---------------- launcher ----------------
extern "C" void kernel_launch(void* const* d_in, const int* in_sizes, int n_in,
                              void* d_out, int out_size) {
    const float* center  = (const float*)d_in[0];
    const float* size_   = (const float*)d_in[1];
    const float* heading = (const float*)d_in[2];
    const float* sxyz    = (const float*)d_in[3];
    const float* sfeat   = (const float*)d_in[4];
    const float* w0  = (const float*)d_in[5];
    const float* b0  = (const float*)d_in[6];
    const float* g0  = (const float*)d_in[7];
    const float* be0 = (const float*)d_in[8];
    const float* w1  = (const float*)d_in[9];
    const float* b1  = (const float*)d_in[10];
    const float* g1  = (const float*)d_in[11];
    const float* be1 = (const float*)d_in[12];
    const float* w2  = (const float*)d_in[13];
    const float* b2  = (const float*)d_in[14];
    const float* g2  = (const float*)d_in[15];
    const float* be2 = (const float*)d_in[16];
    const float* cw1 = (const float*)d_in[17];
    const float* cb1 = (const float*)d_in[18];
    const float* g3  = (const float*)d_in[19];
    const float* be3 = (const float*)d_in[20];
    const float* cw2 = (const float*)d_in[21];
    const float* cb2 = (const float*)d_in[22];
    const float* g4  = (const float*)d_in[23];
    const float* be4 = (const float*)d_in[24];
    const float* cw3 = (const float*)d_in[25];
    const float* cb3 = (const float*)d_in[26];
    float* out = (float*)d_out;

    void *pX0, *pY1, *pY2, *pF, *pN1, *pN2, *pSC, *pSH, *pPart;
    cudaGetSymbolAddress(&pX0, g_X0);
    cudaGetSymbolAddress(&pY1, g_Y1);
    cudaGetSymbolAddress(&pY2, g_Y2);
    cudaGetSymbolAddress(&pF,  g_F);
    cudaGetSymbolAddress(&pN1, g_N1);
    cudaGetSymbolAddress(&pN2, g_N2);
    cudaGetSymbolAddress(&pSC, g_scale);
    cudaGetSymbolAddress(&pSH, g_shift);
    cudaGetSymbolAddress(&pPart, g_part);
    float* X0 = (float*)pX0;
    float* Y1 = (float*)pY1;
    float* Y2 = (float*)pY2;
    float* F  = (float*)pF;
    float* N1 = (float*)pN1;
    float* N2 = (float*)pN2;
    float* SC = (float*)pSC;
    float* SH = (float*)pSH;
    float* PART = (float*)pPart;

    // stage 1: geometry + interpolation inputs
    k_transpose<<<dim3(NS / 32, CF / 32, BB), dim3(32, 8)>>>(sfeat);
    k_gridpoints<<<M1 / 256, 256>>>(center, size_, heading);
    k_threenn<<<BB * 128, 128>>>(sxyz);
    k_interp<<<M1 / 8, 256>>>();

    // stage 2: SharedMLP on tensor cores; BN stats fused into each GEMM epilogue.
    // Last conv layer also fuses the 64-point maxpool (raw max; BN3+ReLU folded into FC1).
    k_gemm_bf<CIN0, false, true, false, true><<<M1 / 128, 256>>>(
        X0, LDA0, w0, b0, nullptr, nullptr, Y1, PART, nullptr);
    k_bnfin512<<<1, 512>>>(1.f / M1, g0, be0, 0);

    k_gemm_bf<HH, true, false, false, true><<<M1 / 128, 256>>>(
        Y1, HH, w1, b1, SC + 0 * 128, SH + 0 * 128, Y2, PART, nullptr);
    k_bnfin512<<<1, 512>>>(1.f / M1, g1, be1, 1);

    k_gemm_bf<HH, true, false, true, false><<<M1 / 128, 256>>>(
        Y2, HH, w2, b2, SC + 1 * 128, SH + 1 * 128, nullptr, PART, F);
    k_bnfin512<<<1, 512>>>(1.f / M1, g2, be2, 2);

    // stage 3: FC head (fp32 SIMT, tiny). FC1 applies BN3+ReLU to the raw pooled features.
    k_gemm<HH, true><<<MFC / 128, 256>>>(F, HH, cw1, cb1, SC + 2 * 128, SH + 2 * 128, N1);
    k_stats<<<8, 256>>>(N1, MFC);
    k_bnfin<<<1, 128>>>(8, 1.f / MFC, g3, be3, 3);

    k_gemm<HH, true><<<MFC / 128, 256>>>(N1, HH, cw2, cb2, SC + 3 * 128, SH + 3 * 128, N2);
    k_stats<<<8, 256>>>(N2, MFC);
    k_bnfin<<<1, 128>>>(8, 1.f / MFC, g4, be4, 4);

    k_final<<<(MFC * IOUS + 255) / 256, 256>>>(cw3, cb3, out);
}

// round 7
// speedup vs baseline: 2.1116x; 1.0744x over previous
#include <cuda_runtime.h>
#include <cuda_bf16.h>
#include <math.h>
#include <stdint.h>

// ---------------- problem constants ----------------
static constexpr int BB   = 4;
static constexpr int KK   = 256;
static constexpr int NS   = 1024;      // seeds
static constexpr int CF   = 256;       // seed feature channels
static constexpr int GPP  = 64;        // grid points per proposal
static constexpr int QQ   = KK * GPP;  // 16384 queries per batch
static constexpr int M1   = BB * QQ;   // 65536 rows for conv layers
static constexpr int CIN0 = CF + 3;    // 259 logical input channels
static constexpr int KPH0 = 288;       // padded logical K for layer0 (9 chunks of 32)
static constexpr int HH   = 128;
static constexpr int MFC  = BB * KK;   // 1024 rows for FC layers
static constexpr int IOUS = 18;
static constexpr int OUTC = 77;

// Layer-0 logical A layout (never materialized): cols [0,256) = interp features
// (gathered on the fly from g_featT), [256,259) = rel xyz, [259,288) = 0.
// Layer-0 W load permutes: phys k<256 -> logical k+3 ; phys 256..258 -> logical k-256.

// ---------------- scratch (static device memory; no allocations) ----------------
__device__ float g_wq[M1 * 3];
__device__ float g_rel[M1 * 3];
__device__ float g_featT[BB * NS * CF];        // [b][n][c]
__device__ int   g_idx3[M1 * 3];
__device__ float g_w3[M1 * 3];
__device__ float g_Y1[(long long)M1 * HH];
__device__ float g_Y2[(long long)M1 * HH];
__device__ float g_F [MFC * HH];               // RAW maxpool output (pre-BN3)
__device__ float g_N1[MFC * HH];
__device__ float g_N2[MFC * HH];
__device__ float g_part[512 * 256];            // per-CTA partial BN stats
__device__ float g_scale[5 * 128];
__device__ float g_shift[5 * 128];

// ---------------- small helpers ----------------
// split two fp32 values into packed-bf16 (hi pair, lo pair); word = {k_even, k_odd}
__device__ __forceinline__ void split2_bf16(float v0, float v1, uint32_t& hi, uint32_t& lo) {
    __nv_bfloat16 h0 = __float2bfloat16_rn(v0);
    __nv_bfloat16 h1 = __float2bfloat16_rn(v1);
    float l0 = v0 - __bfloat162float(h0);
    float l1 = v1 - __bfloat162float(h1);
    __nv_bfloat162 hp = __halves2bfloat162(h0, h1);
    __nv_bfloat162 lp = __floats2bfloat162_rn(l0, l1);
    hi = *reinterpret_cast<uint32_t*>(&hp);
    lo = *reinterpret_cast<uint32_t*>(&lp);
}

__device__ __forceinline__ void mma_bf16(float& c0, float& c1, float& c2, float& c3,
                                         uint32_t a0, uint32_t a1, uint32_t a2, uint32_t a3,
                                         uint32_t b0, uint32_t b1) {
    asm volatile(
        "mma.sync.aligned.m16n8k16.row.col.f32.bf16.bf16.f32 "
        "{%0,%1,%2,%3}, {%4,%5,%6,%7}, {%8,%9}, {%0,%1,%2,%3};"
        : "+f"(c0), "+f"(c1), "+f"(c2), "+f"(c3)
        : "r"(a0), "r"(a1), "r"(a2), "r"(a3), "r"(b0), "r"(b1));
}

// ---------------- kernels ----------------

// seed_features [b][c][n] -> g_featT [b][n][c]
__global__ void k_transpose(const float* __restrict__ feat) {
    __shared__ float tile[32][33];
    int b  = blockIdx.z;
    int n0 = blockIdx.x * 32;
    int c0 = blockIdx.y * 32;
    const float* src = feat    + (long long)b * CF * NS;
    float*       dst = g_featT + (long long)b * NS * CF;
#pragma unroll
    for (int r = 0; r < 4; ++r) {
        int c = c0 + threadIdx.y + r * 8;
        tile[threadIdx.y + r * 8][threadIdx.x] = src[c * NS + n0 + threadIdx.x];
    }
    __syncthreads();
#pragma unroll
    for (int r = 0; r < 4; ++r) {
        int n = n0 + threadIdx.y + r * 8;
        dst[n * CF + c0 + threadIdx.x] = tile[threadIdx.x][threadIdx.y + r * 8];
    }
}

// rotate+scale grid -> g_rel, world points -> g_wq
__global__ void k_gridpoints(const float* __restrict__ center,
                             const float* __restrict__ size_,
                             const float* __restrict__ heading) {
    int m = blockIdx.x * blockDim.x + threadIdx.x;
    if (m >= M1) return;
    int g  = m & 63;
    int bk = m >> 6;
    float sx = size_[bk * 3 + 0], sy = size_[bk * 3 + 1], sz = size_[bk * 3 + 2];
    float h  = heading[bk];
    float ch = cosf(h), sh = sinf(h);
    float gx = -1.f + (float)( g >> 4      ) * (2.f / 3.f);
    float gy = -1.f + (float)((g >> 2) & 3 ) * (2.f / 3.f);
    float gz = -1.f + (float)( g       & 3 ) * (2.f / 3.f);
    float ax = gx * sx, ay = gy * sy, az = gz * sz;
    float rx = ax * ch - ay * sh;
    float ry = ax * sh + ay * ch;
    float rz = az;
    g_rel[m * 3 + 0] = rx;
    g_rel[m * 3 + 1] = ry;
    g_rel[m * 3 + 2] = rz;
    g_wq[m * 3 + 0] = rx + center[bk * 3 + 0];
    g_wq[m * 3 + 1] = ry + center[bk * 3 + 1];
    g_wq[m * 3 + 2] = rz + center[bk * 3 + 2];
}

// 3-NN per query over 1024 seeds (seeds cached in SMEM), inverse-distance weights
__global__ void k_threenn(const float* __restrict__ seed_xyz) {
    __shared__ float4 sp[NS];
    int b = blockIdx.x >> 7;
    int q = ((blockIdx.x & 127) << 7) + threadIdx.x;
    for (int i = threadIdx.x; i < NS; i += blockDim.x) {
        float x = seed_xyz[((long long)b * NS + i) * 3 + 0];
        float y = seed_xyz[((long long)b * NS + i) * 3 + 1];
        float z = seed_xyz[((long long)b * NS + i) * 3 + 2];
        sp[i] = make_float4(x, y, z, x * x + y * y + z * z);
    }
    __syncthreads();
    int m = b * QQ + q;
    float qx = g_wq[m * 3 + 0], qy = g_wq[m * 3 + 1], qz = g_wq[m * 3 + 2];
    float qq = qx * qx + qy * qy + qz * qz;
    float d0 = 1e30f, d1 = 1e30f, d2 = 1e30f;
    int   i0 = 0, i1 = 0, i2 = 0;
    for (int n = 0; n < NS; ++n) {
        float4 p = sp[n];
        float d = qq + p.w - 2.f * (qx * p.x + qy * p.y + qz * p.z);
        if (d < d2) {
            if (d < d1) {
                d2 = d1; i2 = i1;
                if (d < d0) { d1 = d0; i1 = i0; d0 = d; i0 = n; }
                else        { d1 = d;  i1 = n; }
            } else { d2 = d; i2 = n; }
        }
    }
    int ii[3] = {i0, i1, i2};
    float w[3];
#pragma unroll
    for (int j = 0; j < 3; ++j) {
        float4 p = sp[ii[j]];
        float dx = p.x - qx, dy = p.y - qy, dz = p.z - qz;
        float dist = sqrtf(dx * dx + dy * dy + dz * dz);
        w[j] = 1.f / (dist + 1e-8f);
    }
    float inv = 1.f / (w[0] + w[1] + w[2]);
#pragma unroll
    for (int j = 0; j < 3; ++j) {
        g_idx3[m * 3 + j] = ii[j];
        g_w3[m * 3 + j]   = w[j] * inv;
    }
}

// ---- split-bf16 tensor-core GEMM with fused epilogue (and optional fused gather) ----
// C[m,n] = sum_k act(A[m,k]) * W[n,k] + bias[n]
// 128x128 tile, K-chunks of 32, m16n8k16 bf16 MMA, acc += aL*bH + aH*bL + aH*bH.
// 8 warps (2 over M x 4 over N).
// GATHER: layer-0 mode. A is never materialized; each thread gathers its row's
//   features as w0*featT[i0] + w1*featT[i1] + w2*featT[i2] (L2-hot), rel xyz at
//   k=256..258, zeros beyond. No prefetch (register budget); L2 covers latency.
// !GATHER: A-chunk register-prefetched one iteration ahead.
// Epilogue always emits per-CTA partial BN stats (sum, sumsq per channel) to partOut.
// POOL: also emit per-64-row-group raw channel max to poolOut (2 proposals per CTA).
// STOREC: write C tile to GMEM.
template <int KDIM, bool BNA, bool GATHER, bool POOL, bool STOREC>
__global__ void __launch_bounds__(256, 2)
k_gemm_bf(const float* __restrict__ A, int lda,
          const float* __restrict__ W,
          const float* __restrict__ bias,
          const float* __restrict__ scl,
          const float* __restrict__ shf,
          float* __restrict__ C,
          float* __restrict__ partOut,
          float* __restrict__ poolOut) {
    __shared__ uint32_t AsH[16][136];
    __shared__ uint32_t AsL[16][136];
    __shared__ uint32_t WsH[16][136];
    __shared__ uint32_t WsL[16][136];
    __shared__ float redS[2][128];
    __shared__ float redQ[2][128];
    __shared__ float redM[2][128];

    const int tid  = threadIdx.x;
    const int lane = tid & 31;
    const int warp = tid >> 5;
    const int g    = lane >> 2;        // 0..7
    const int q    = lane & 3;         // 0..3
    const int wm   = warp & 1;         // 2 warps over M
    const int wn   = warp >> 1;        // 4 warps over N
    const int bm   = blockIdx.x * 128;

    float acc[4][4][4];
#pragma unroll
    for (int i = 0; i < 4; ++i)
#pragma unroll
        for (int j = 0; j < 4; ++j)
#pragma unroll
            for (int r = 0; r < 4; ++r) acc[i][j][r] = 0.f;

    const int ldrow = tid >> 1;         // 0..127
    const int ldkv  = (tid & 1) * 16;   // 0 or 16
    const int KPHYS = GATHER ? KPH0 : KDIM;
    const int NCH   = KPHYS / 32;       // 9 for layer0, 4 for K=128

    // GATHER mode: per-row gather state (row fixed for whole k-loop)
    const float *gf0 = nullptr, *gf1 = nullptr, *gf2 = nullptr;
    float gw0 = 0.f, gw1 = 0.f, gw2 = 0.f;
    float grel[3] = {0.f, 0.f, 0.f};
    if (GATHER) {
        const int m = bm + ldrow;
        const int b = m >> 14;  // / QQ
        int i0 = g_idx3[m * 3 + 0], i1 = g_idx3[m * 3 + 1], i2 = g_idx3[m * 3 + 2];
        gw0 = g_w3[m * 3 + 0]; gw1 = g_w3[m * 3 + 1]; gw2 = g_w3[m * 3 + 2];
        gf0 = g_featT + ((long long)b * NS + i0) * CF;
        gf1 = g_featT + ((long long)b * NS + i1) * CF;
        gf2 = g_featT + ((long long)b * NS + i2) * CF;
        grel[0] = g_rel[m * 3 + 0];
        grel[1] = g_rel[m * 3 + 1];
        grel[2] = g_rel[m * 3 + 2];
    }

    float vA[16];
    if (!GATHER) {
        // prefetch chunk 0
        const float* ap = A + (long long)(bm + ldrow) * lda + ldkv;
        float4 u0 = *(const float4*)(ap + 0);
        float4 u1 = *(const float4*)(ap + 4);
        float4 u2 = *(const float4*)(ap + 8);
        float4 u3 = *(const float4*)(ap + 12);
        vA[0]=u0.x; vA[1]=u0.y; vA[2]=u0.z; vA[3]=u0.w;
        vA[4]=u1.x; vA[5]=u1.y; vA[6]=u1.z; vA[7]=u1.w;
        vA[8]=u2.x; vA[9]=u2.y; vA[10]=u2.z; vA[11]=u2.w;
        vA[12]=u3.x; vA[13]=u3.y; vA[14]=u3.z; vA[15]=u3.w;
    }

    for (int ch = 0; ch < NCH; ++ch) {
        const int k0 = ch * 32;
        // ---- build + split A chunk -> SMEM ----
        {
            float v[16];
            if (GATHER) {
                const int kbase = k0 + ldkv;
                if (kbase < 256) {
#pragma unroll
                    for (int r4 = 0; r4 < 4; ++r4) {
                        float4 a = *(const float4*)(gf0 + kbase + r4 * 4);
                        float4 bq = *(const float4*)(gf1 + kbase + r4 * 4);
                        float4 cq = *(const float4*)(gf2 + kbase + r4 * 4);
                        v[r4 * 4 + 0] = gw0 * a.x + gw1 * bq.x + gw2 * cq.x;
                        v[r4 * 4 + 1] = gw0 * a.y + gw1 * bq.y + gw2 * cq.y;
                        v[r4 * 4 + 2] = gw0 * a.z + gw1 * bq.z + gw2 * cq.z;
                        v[r4 * 4 + 3] = gw0 * a.w + gw1 * bq.w + gw2 * cq.w;
                    }
                } else {
                    // kbase == 256 (rel xyz + zeros) or 272 (all zeros)
#pragma unroll
                    for (int i = 0; i < 16; ++i) v[i] = 0.f;
                    if (kbase == 256) { v[0] = grel[0]; v[1] = grel[1]; v[2] = grel[2]; }
                }
            } else {
#pragma unroll
                for (int i = 0; i < 16; ++i) v[i] = vA[i];
                if (BNA) {
#pragma unroll
                    for (int i = 0; i < 16; ++i) {
                        int k = k0 + ldkv + i;   // BNA only with KDIM=128: always valid
                        v[i] = fmaxf(v[i] * scl[k] + shf[k], 0.f);
                    }
                }
            }
            const int kp0 = ldkv / 2;
#pragma unroll
            for (int i = 0; i < 8; ++i) {
                uint32_t hi, lo;
                split2_bf16(v[2 * i], v[2 * i + 1], hi, lo);
                AsH[kp0 + i][ldrow] = hi;
                AsL[kp0 + i][ldrow] = lo;
            }
        }
        // ---- W tile (L2-hot) -> SMEM ----
        {
            const int n = ldrow;
            float v[16];
            if (GATHER) {
                // layer-0 W permutation: logical col kl for phys k
#pragma unroll
                for (int i = 0; i < 16; ++i) {
                    int k = k0 + ldkv + i;
                    v[i] = 0.f;
                    if (k < CIN0) {
                        int kl = (k < 256) ? (k + 3) : (k - 256);
                        v[i] = W[n * CIN0 + kl];
                    }
                }
            } else {
                const float* wp = W + (long long)n * KDIM + k0 + ldkv;
                float4 u0 = *(const float4*)(wp + 0);
                float4 u1 = *(const float4*)(wp + 4);
                float4 u2 = *(const float4*)(wp + 8);
                float4 u3 = *(const float4*)(wp + 12);
                v[0]=u0.x; v[1]=u0.y; v[2]=u0.z; v[3]=u0.w;
                v[4]=u1.x; v[5]=u1.y; v[6]=u1.z; v[7]=u1.w;
                v[8]=u2.x; v[9]=u2.y; v[10]=u2.z; v[11]=u2.w;
                v[12]=u3.x; v[13]=u3.y; v[14]=u3.z; v[15]=u3.w;
            }
            const int kp0 = ldkv / 2;
#pragma unroll
            for (int i = 0; i < 8; ++i) {
                uint32_t hi, lo;
                split2_bf16(v[2 * i], v[2 * i + 1], hi, lo);
                WsH[kp0 + i][n] = hi;
                WsL[kp0 + i][n] = lo;
            }
        }
        __syncthreads();

        // ---- prefetch next A chunk (non-gather path only) ----
        if (!GATHER && ch + 1 < NCH) {
            const float* ap = A + (long long)(bm + ldrow) * lda + (k0 + 32) + ldkv;
            float4 u0 = *(const float4*)(ap + 0);
            float4 u1 = *(const float4*)(ap + 4);
            float4 u2 = *(const float4*)(ap + 8);
            float4 u3 = *(const float4*)(ap + 12);
            vA[0]=u0.x; vA[1]=u0.y; vA[2]=u0.z; vA[3]=u0.w;
            vA[4]=u1.x; vA[5]=u1.y; vA[6]=u1.z; vA[7]=u1.w;
            vA[8]=u2.x; vA[9]=u2.y; vA[10]=u2.z; vA[11]=u2.w;
            vA[12]=u3.x; vA[13]=u3.y; vA[14]=u3.z; vA[15]=u3.w;
        }

        // ---- two k16 steps per chunk ----
#pragma unroll
        for (int kb = 0; kb < 16; kb += 8) {
            uint32_t bH[4][2], bL[4][2];
#pragma unroll
            for (int nt = 0; nt < 4; ++nt) {
                int nbase = wn * 32 + nt * 8;
                bH[nt][0] = WsH[kb + q    ][nbase + g];
                bH[nt][1] = WsH[kb + q + 4][nbase + g];
                bL[nt][0] = WsL[kb + q    ][nbase + g];
                bL[nt][1] = WsL[kb + q + 4][nbase + g];
            }
#pragma unroll
            for (int mt = 0; mt < 4; ++mt) {
                int mbase = wm * 64 + mt * 16;
                uint32_t aH0 = AsH[kb + q    ][mbase + g    ];
                uint32_t aH1 = AsH[kb + q    ][mbase + g + 8];
                uint32_t aH2 = AsH[kb + q + 4][mbase + g    ];
                uint32_t aH3 = AsH[kb + q + 4][mbase + g + 8];
                uint32_t aL0 = AsL[kb + q    ][mbase + g    ];
                uint32_t aL1 = AsL[kb + q    ][mbase + g + 8];
                uint32_t aL2 = AsL[kb + q + 4][mbase + g    ];
                uint32_t aL3 = AsL[kb + q + 4][mbase + g + 8];
#pragma unroll
                for (int nt = 0; nt < 4; ++nt) {
                    mma_bf16(acc[mt][nt][0], acc[mt][nt][1], acc[mt][nt][2], acc[mt][nt][3],
                             aL0, aL1, aL2, aL3, bH[nt][0], bH[nt][1]);
                    mma_bf16(acc[mt][nt][0], acc[mt][nt][1], acc[mt][nt][2], acc[mt][nt][3],
                             aH0, aH1, aH2, aH3, bL[nt][0], bL[nt][1]);
                    mma_bf16(acc[mt][nt][0], acc[mt][nt][1], acc[mt][nt][2], acc[mt][nt][3],
                             aH0, aH1, aH2, aH3, bH[nt][0], bH[nt][1]);
                }
            }
        }
        __syncthreads();
    }

    // ---- fused epilogue: bias, optional store, BN stats partials, optional maxpool ----
    float bsv[4][2];
#pragma unroll
    for (int nt = 0; nt < 4; ++nt) {
        int col = wn * 32 + nt * 8 + q * 2;
        bsv[nt][0] = bias[col];
        bsv[nt][1] = bias[col + 1];
    }
    float s[4][2], s2[4][2], mx[4][2];
#pragma unroll
    for (int nt = 0; nt < 4; ++nt)
#pragma unroll
        for (int j = 0; j < 2; ++j) { s[nt][j] = 0.f; s2[nt][j] = 0.f; mx[nt][j] = -1e30f; }

#pragma unroll
    for (int mt = 0; mt < 4; ++mt) {
#pragma unroll
        for (int nt = 0; nt < 4; ++nt) {
            float v0 = acc[mt][nt][0] + bsv[nt][0];
            float v1 = acc[mt][nt][1] + bsv[nt][1];
            float v2 = acc[mt][nt][2] + bsv[nt][0];
            float v3 = acc[mt][nt][3] + bsv[nt][1];
            if (STOREC) {
                int col = wn * 32 + nt * 8 + q * 2;
                int r0  = bm + wm * 64 + mt * 16 + g;
                *(float2*)(C + (long long)r0 * 128 + col)       = make_float2(v0, v1);
                *(float2*)(C + (long long)(r0 + 8) * 128 + col) = make_float2(v2, v3);
            }
            s [nt][0] += v0 + v2;       s [nt][1] += v1 + v3;
            s2[nt][0] += v0 * v0 + v2 * v2;
            s2[nt][1] += v1 * v1 + v3 * v3;
            if (POOL) {
                mx[nt][0] = fmaxf(mx[nt][0], fmaxf(v0, v2));
                mx[nt][1] = fmaxf(mx[nt][1], fmaxf(v1, v3));
            }
        }
    }
    // reduce across the 8 g-lanes (lane = g*4+q; g bits are lane bits 2..4)
#pragma unroll
    for (int nt = 0; nt < 4; ++nt)
#pragma unroll
        for (int j = 0; j < 2; ++j) {
#pragma unroll
            for (int mask = 4; mask <= 16; mask <<= 1) {
                s [nt][j] += __shfl_xor_sync(0xffffffff, s [nt][j], mask);
                s2[nt][j] += __shfl_xor_sync(0xffffffff, s2[nt][j], mask);
                if (POOL)
                    mx[nt][j] = fmaxf(mx[nt][j], __shfl_xor_sync(0xffffffff, mx[nt][j], mask));
            }
        }
    if (g == 0) {
#pragma unroll
        for (int nt = 0; nt < 4; ++nt)
#pragma unroll
            for (int j = 0; j < 2; ++j) {
                int col = wn * 32 + nt * 8 + q * 2 + j;
                redS[wm][col] = s[nt][j];
                redQ[wm][col] = s2[nt][j];
                if (POOL) redM[wm][col] = mx[nt][j];
            }
    }
    __syncthreads();
    if (tid < 128) {
        partOut[blockIdx.x * 256 + tid]       = redS[0][tid] + redS[1][tid];
        partOut[blockIdx.x * 256 + 128 + tid] = redQ[0][tid] + redQ[1][tid];
    }
    if (POOL) {
        // proposal bk = blockIdx*2 + wm-group; raw max (BN3+ReLU applied later via FC1 BNA)
        poolOut[(blockIdx.x * 2 + (tid >> 7)) * 128 + (tid & 127)] = redM[tid >> 7][tid & 127];
    }
}

// reduce 512 per-CTA partials -> folded BN scale/shift (1 block, 512 threads)
__global__ void k_bnfin512(float Minv,
                           const float* __restrict__ gamma,
                           const float* __restrict__ beta,
                           int slot) {
    __shared__ float rs[4][128], rq[4][128];
    int c  = threadIdx.x & 127;
    int sl = threadIdx.x >> 7;
    float s = 0.f, q = 0.f;
    for (int b = sl * 128; b < sl * 128 + 128; ++b) {
        s += g_part[b * 256 + c];
        q += g_part[b * 256 + 128 + c];
    }
    rs[sl][c] = s; rq[sl][c] = q;
    __syncthreads();
    if (threadIdx.x < 128) {
        float S = rs[0][c] + rs[1][c] + rs[2][c] + rs[3][c];
        float Q = rq[0][c] + rq[1][c] + rq[2][c] + rq[3][c];
        float mean = S * Minv;
        float var  = Q * Minv - mean * mean;
        float rstd = rsqrtf(var + 1e-5f);
        float sc   = gamma[c] * rstd;
        g_scale[slot * 128 + c] = sc;
        g_shift[slot * 128 + c] = beta[c] - mean * sc;
    }
}

// -------- fp32 SIMT GEMM for the tiny FC layers (M=1024) --------
template <int KDIM, bool BNA>
__global__ void __launch_bounds__(256)
k_gemm(const float* __restrict__ A, int lda,
       const float* __restrict__ W,
       const float* __restrict__ bias,
       const float* __restrict__ scl,
       const float* __restrict__ shf,
       float* __restrict__ C) {
    __shared__ float As[16][128];
    __shared__ float Ws2[16][128];
    int tid = threadIdx.x;
    int bm  = blockIdx.x * 128;
    int tx  = tid & 15, ty = tid >> 4;
    float acc[8][8];
#pragma unroll
    for (int i = 0; i < 8; ++i)
#pragma unroll
        for (int j = 0; j < 8; ++j) acc[i][j] = 0.f;

    const int KT = (KDIM + 15) / 16;
    for (int kt = 0; kt < KT; ++kt) {
        int k0 = kt * 16;
#pragma unroll
        for (int r = 0; r < 2; ++r) {
            int row = (tid >> 2) + r * 64;
            int kv  = (tid & 3) * 4;
            int k   = k0 + kv;
            float4 v = *reinterpret_cast<const float4*>(A + (long long)(bm + row) * lda + k);
            if (BNA) {
                v.x = fmaxf(v.x * scl[k + 0] + shf[k + 0], 0.f);
                v.y = fmaxf(v.y * scl[k + 1] + shf[k + 1], 0.f);
                v.z = fmaxf(v.z * scl[k + 2] + shf[k + 2], 0.f);
                v.w = fmaxf(v.w * scl[k + 3] + shf[k + 3], 0.f);
            }
            As[kv + 0][row] = v.x;
            As[kv + 1][row] = v.y;
            As[kv + 2][row] = v.z;
            As[kv + 3][row] = v.w;
        }
        {
            int n  = tid >> 1;
            int kb = (tid & 1) * 8;
#pragma unroll
            for (int i = 0; i < 8; ++i) {
                int k = k0 + kb + i;
                Ws2[kb + i][n] = W[n * KDIM + k];
            }
        }
        __syncthreads();
#pragma unroll
        for (int kk = 0; kk < 16; ++kk) {
            float a[8], w8[8];
            *reinterpret_cast<float4*>(&a[0])  = *reinterpret_cast<const float4*>(&As[kk][ty * 8]);
            *reinterpret_cast<float4*>(&a[4])  = *reinterpret_cast<const float4*>(&As[kk][ty * 8 + 4]);
            *reinterpret_cast<float4*>(&w8[0]) = *reinterpret_cast<const float4*>(&Ws2[kk][tx * 8]);
            *reinterpret_cast<float4*>(&w8[4]) = *reinterpret_cast<const float4*>(&Ws2[kk][tx * 8 + 4]);
#pragma unroll
            for (int i = 0; i < 8; ++i)
#pragma unroll
                for (int j = 0; j < 8; ++j) acc[i][j] += a[i] * w8[j];
        }
        __syncthreads();
    }
    float bv[8];
#pragma unroll
    for (int j = 0; j < 8; ++j) bv[j] = bias[tx * 8 + j];
#pragma unroll
    for (int i = 0; i < 8; ++i) {
        long long off = (long long)(bm + ty * 8 + i) * 128 + tx * 8;
        float4 o0 = make_float4(acc[i][0] + bv[0], acc[i][1] + bv[1],
                                acc[i][2] + bv[2], acc[i][3] + bv[3]);
        float4 o1 = make_float4(acc[i][4] + bv[4], acc[i][5] + bv[5],
                                acc[i][6] + bv[6], acc[i][7] + bv[7]);
        *reinterpret_cast<float4*>(C + off)     = o0;
        *reinterpret_cast<float4*>(C + off + 4) = o1;
    }
}

// deterministic two-stage BN stats for FC layers (small)
__global__ void k_stats(const float* __restrict__ Y, int M) {
    __shared__ float ss[256], sq[256];
    int c    = threadIdx.x & 127;
    int half = threadIdx.x >> 7;
    int rowsPer = M / gridDim.x;
    int r0 = blockIdx.x * rowsPer;
    float s = 0.f, s2 = 0.f;
    for (int r = r0 + half; r < r0 + rowsPer; r += 2) {
        float v = Y[(long long)r * 128 + c];
        s += v; s2 += v * v;
    }
    ss[threadIdx.x] = s; sq[threadIdx.x] = s2;
    __syncthreads();
    if (threadIdx.x < 128) {
        g_part[blockIdx.x * 256 + threadIdx.x]       = ss[threadIdx.x] + ss[threadIdx.x + 128];
        g_part[blockIdx.x * 256 + 128 + threadIdx.x] = sq[threadIdx.x] + sq[threadIdx.x + 128];
    }
}

__global__ void k_bnfin(int NB, float Minv,
                        const float* __restrict__ gamma,
                        const float* __restrict__ beta,
                        int slot) {
    int c = threadIdx.x;
    float s = 0.f, s2 = 0.f;
    for (int b = 0; b < NB; ++b) {
        s  += g_part[b * 256 + c];
        s2 += g_part[b * 256 + 128 + c];
    }
    float mean = s * Minv;
    float var  = s2 * Minv - mean * mean;
    float rstd = rsqrtf(var + 1e-5f);
    float sc   = gamma[c] * rstd;
    g_scale[slot * 128 + c] = sc;
    g_shift[slot * 128 + c] = beta[c] - mean * sc;
}

// BN5+ReLU on N2, project to the last 18 of 77 output channels
__global__ void k_final(const float* __restrict__ cw3,
                        const float* __restrict__ cb3,
                        float* __restrict__ out) {
    int t = blockIdx.x * blockDim.x + threadIdx.x;
    if (t >= MFC * IOUS) return;
    int j   = t % IOUS;
    int row = t / IOUS;
    int o   = (OUTC - IOUS) + j;
    const float* wrow = cw3 + o * 128;
    const float* x    = g_N2 + row * 128;
    float acc = cb3[o];
#pragma unroll 8
    for (int i = 0; i < 128; ++i) {
        float v = fmaxf(x[i] * g_scale[4 * 128 + i] + g_shift[4 * 128 + i], 0.f);
        acc += v * wrow[i];
    }
    out[t] = acc;
}

// ---------------- launcher ----------------
extern "C" void kernel_launch(void* const* d_in, const int* in_sizes, int n_in,
                              void* d_out, int out_size) {
    const float* center  = (const float*)d_in[0];
    const float* size_   = (const float*)d_in[1];
    const float* heading = (const float*)d_in[2];
    const float* sxyz    = (const float*)d_in[3];
    const float* sfeat   = (const float*)d_in[4];
    const float* w0  = (const float*)d_in[5];
    const float* b0  = (const float*)d_in[6];
    const float* g0  = (const float*)d_in[7];
    const float* be0 = (const float*)d_in[8];
    const float* w1  = (const float*)d_in[9];
    const float* b1  = (const float*)d_in[10];
    const float* g1  = (const float*)d_in[11];
    const float* be1 = (const float*)d_in[12];
    const float* w2  = (const float*)d_in[13];
    const float* b2  = (const float*)d_in[14];
    const float* g2  = (const float*)d_in[15];
    const float* be2 = (const float*)d_in[16];
    const float* cw1 = (const float*)d_in[17];
    const float* cb1 = (const float*)d_in[18];
    const float* g3  = (const float*)d_in[19];
    const float* be3 = (const float*)d_in[20];
    const float* cw2 = (const float*)d_in[21];
    const float* cb2 = (const float*)d_in[22];
    const float* g4  = (const float*)d_in[23];
    const float* be4 = (const float*)d_in[24];
    const float* cw3 = (const float*)d_in[25];
    const float* cb3 = (const float*)d_in[26];
    float* out = (float*)d_out;

    void *pY1, *pY2, *pF, *pN1, *pN2, *pSC, *pSH, *pPart;
    cudaGetSymbolAddress(&pY1, g_Y1);
    cudaGetSymbolAddress(&pY2, g_Y2);
    cudaGetSymbolAddress(&pF,  g_F);
    cudaGetSymbolAddress(&pN1, g_N1);
    cudaGetSymbolAddress(&pN2, g_N2);
    cudaGetSymbolAddress(&pSC, g_scale);
    cudaGetSymbolAddress(&pSH, g_shift);
    cudaGetSymbolAddress(&pPart, g_part);
    float* Y1 = (float*)pY1;
    float* Y2 = (float*)pY2;
    float* F  = (float*)pF;
    float* N1 = (float*)pN1;
    float* N2 = (float*)pN2;
    float* SC = (float*)pSC;
    float* SH = (float*)pSH;
    float* PART = (float*)pPart;

    // stage 1: geometry + 3-NN (interp is fused into GEMM0's A-loader)
    k_transpose<<<dim3(NS / 32, CF / 32, BB), dim3(32, 8)>>>(sfeat);
    k_gridpoints<<<M1 / 256, 256>>>(center, size_, heading);
    k_threenn<<<BB * 128, 128>>>(sxyz);

    // stage 2: SharedMLP on tensor cores; BN stats fused into each GEMM epilogue.
    // Layer0 gathers its input on the fly (GATHER). Last conv layer fuses the
    // 64-point maxpool (raw max; BN3+ReLU folded into FC1).
    k_gemm_bf<CIN0, false, true, false, true><<<M1 / 128, 256>>>(
        nullptr, 0, w0, b0, nullptr, nullptr, Y1, PART, nullptr);
    k_bnfin512<<<1, 512>>>(1.f / M1, g0, be0, 0);

    k_gemm_bf<HH, true, false, false, true><<<M1 / 128, 256>>>(
        Y1, HH, w1, b1, SC + 0 * 128, SH + 0 * 128, Y2, PART, nullptr);
    k_bnfin512<<<1, 512>>>(1.f / M1, g1, be1, 1);

    k_gemm_bf<HH, true, false, true, false><<<M1 / 128, 256>>>(
        Y2, HH, w2, b2, SC + 1 * 128, SH + 1 * 128, nullptr, PART, F);
    k_bnfin512<<<1, 512>>>(1.f / M1, g2, be2, 2);

    // stage 3: FC head (fp32 SIMT, tiny). FC1 applies BN3+ReLU to the raw pooled features.
    k_gemm<HH, true><<<MFC / 128, 256>>>(F, HH, cw1, cb1, SC + 2 * 128, SH + 2 * 128, N1);
    k_stats<<<8, 256>>>(N1, MFC);
    k_bnfin<<<1, 128>>>(8, 1.f / MFC, g3, be3, 3);

    k_gemm<HH, true><<<MFC / 128, 256>>>(N1, HH, cw2, cb2, SC + 3 * 128, SH + 3 * 128, N2);
    k_stats<<<8, 256>>>(N2, MFC);
    k_bnfin<<<1, 128>>>(8, 1.f / MFC, g4, be4, 4);

    k_final<<<(MFC * IOUS + 255) / 256, 256>>>(cw3, cb3, out);
}